// round 5
// baseline (speedup 1.0000x reference)
#include <cuda_runtime.h>

#define N_PATHS 65536
#define N_STEPS 512
#define TPB     64
#define WARPS   (TPB/32)     // 2
#define PPT     2            // paths per thread (f32x2 lanes)
#define TILE    16

// ---- constants (match reference float32 semantics) ----
#define DT_F        (1.0f/252.0f)
#define SQRT_DT_F   0.06299407883487120f     // sqrt(1/252)
#define KAPPA_F     2.72f
#define THETA_F     (-3.5f)
#define SIGMA_P_F   0.85f
#define RHO_F       (-0.85f)
#define CS_F        (0.5267826876426369f * 0.06299407883487120f) // sqrt(1-rho^2)*sqrt_dt
#define R_F         0.0373f
#define LAMBDA_MAX_F 3.0f
#define LOG_V_MIN_F (-7.0f)
#define LOG_V_MAX_F 2.0f
#define INV_NSTEPS  (1.0f/512.0f)

typedef unsigned long long ull;

// ---- packed f32x2 helpers (Blackwell fma.rn.f32x2 — ptxas won't auto-fuse) ----
__device__ __forceinline__ ull pack2(float a, float b) {
    ull r; asm("mov.b64 %0, {%1, %2};" : "=l"(r) : "f"(a), "f"(b)); return r;
}
__device__ __forceinline__ void unpack2(ull v, float& a, float& b) {
    asm("mov.b64 {%0, %1}, %2;" : "=f"(a), "=f"(b) : "l"(v));
}
__device__ __forceinline__ ull fma2(ull a, ull b, ull c) {
    ull d; asm("fma.rn.f32x2 %0, %1, %2, %3;" : "=l"(d) : "l"(a), "l"(b), "l"(c)); return d;
}
__device__ __forceinline__ ull mul2(ull a, ull b) {
    ull d; asm("mul.rn.f32x2 %0, %1, %2;" : "=l"(d) : "l"(a), "l"(b)); return d;
}

__device__ __forceinline__ float fast_tanh(float x) {
    float y;
    asm("tanh.approx.f32 %0, %1;" : "=f"(y) : "f"(x));
    return y;
}

// 5-op gelu on a pair: gelu(x) = fma(0.5x, tanh(u), 0.5x), u = x*(a*x^2+b)
__device__ __forceinline__ ull gelu2(ull x, ull GA, ull GB, ull GH) {
    ull x2 = mul2(x, x);
    ull u  = mul2(x, fma2(GA, x2, GB));
    ull hx = mul2(GH, x);
    float ulo, uhi; unpack2(u, ulo, uhi);
    ull tp = pack2(fast_tanh(ulo), fast_tanh(uhi));
    return fma2(hx, tp, hx);
}

// scalar SDE update per path (identical numerics to validated R3/R4 kernels)
__device__ __forceinline__ void sde_step(float lam, float z1s, float z2s,
                                         float& lv, float& ls, float& lsq,
                                         float& o_lv, float& o_sp)
{
    float dwv = SQRT_DT_F * z1s;
    float dws = fmaf(RHO_F, dwv, CS_F * z2s);
    float mu_p    = (KAPPA_F * (THETA_F - lv)) * DT_F;
    float drift_q = mu_p - (lam * SIGMA_P_F) * DT_F;
    float lv_next = lv + drift_q + SIGMA_P_F * dwv;
    lv_next = fminf(fmaxf(lv_next, LOG_V_MIN_F), LOG_V_MAX_F);
    float ev  = __expf(lv);
    float vol = sqrtf(fmaxf(ev, 1e-10f));
    float ls_next = ls + (R_F - 0.5f * ev) * DT_F + vol * dws;
    lsq = fmaf(lam * lam, DT_F, lsq);
    o_lv = lv_next;
    o_sp = __expf(ls_next);
    lv = lv_next;
    ls = ls_next;
}

// Accumulate one group of 4 neurons (j0..j0+3) of layer 2 into a0..a3.
__device__ __forceinline__ void layer2_group(const float4* __restrict__ W2v,
                                             const ull* __restrict__ sb2d,
                                             const ull* __restrict__ h1,
                                             int j0, ull& a0, ull& a1, ull& a2, ull& a3)
{
    a0 = sb2d[j0 + 0];
    a1 = sb2d[j0 + 1];
    a2 = sb2d[j0 + 2];
    a3 = sb2d[j0 + 3];
    #pragma unroll
    for (int k4 = 0; k4 < 8; k4++) {
        ull h0 = h1[4 * k4 + 0];
        ull hA = h1[4 * k4 + 1];
        ull hB = h1[4 * k4 + 2];
        ull hC = h1[4 * k4 + 3];
        float4 q0 = W2v[(j0 + 0) * 8 + k4];
        float4 q1 = W2v[(j0 + 1) * 8 + k4];
        float4 q2 = W2v[(j0 + 2) * 8 + k4];
        float4 q3 = W2v[(j0 + 3) * 8 + k4];
        a0 = fma2(pack2(q0.x, q0.x), h0, a0);
        a0 = fma2(pack2(q0.y, q0.y), hA, a0);
        a0 = fma2(pack2(q0.z, q0.z), hB, a0);
        a0 = fma2(pack2(q0.w, q0.w), hC, a0);
        a1 = fma2(pack2(q1.x, q1.x), h0, a1);
        a1 = fma2(pack2(q1.y, q1.y), hA, a1);
        a1 = fma2(pack2(q1.z, q1.z), hB, a1);
        a1 = fma2(pack2(q1.w, q1.w), hC, a1);
        a2 = fma2(pack2(q2.x, q2.x), h0, a2);
        a2 = fma2(pack2(q2.y, q2.y), hA, a2);
        a2 = fma2(pack2(q2.z, q2.z), hB, a2);
        a2 = fma2(pack2(q2.w, q2.w), hC, a2);
        a3 = fma2(pack2(q3.x, q3.x), h0, a3);
        a3 = fma2(pack2(q3.y, q3.y), hA, a3);
        a3 = fma2(pack2(q3.z, q3.z), hB, a3);
        a3 = fma2(pack2(q3.w, q3.w), hC, a3);
    }
}

// Start the gelu epilogue for a group: compute 0.5*a and ISSUE the tanh MUFUs.
__device__ __forceinline__ void epi_issue(ull a0, ull a1, ull a2, ull a3,
                                          ull GA, ull GB, ull GH,
                                          ull& hx0, ull& hx1, ull& hx2, ull& hx3,
                                          float* pt /*[8]*/)
{
    ull u0 = mul2(a0, fma2(GA, mul2(a0, a0), GB));
    ull u1 = mul2(a1, fma2(GA, mul2(a1, a1), GB));
    ull u2 = mul2(a2, fma2(GA, mul2(a2, a2), GB));
    ull u3 = mul2(a3, fma2(GA, mul2(a3, a3), GB));
    hx0 = mul2(GH, a0);
    hx1 = mul2(GH, a1);
    hx2 = mul2(GH, a2);
    hx3 = mul2(GH, a3);
    float l0, h0, l1, h1, l2, h2, l3, h3;
    unpack2(u0, l0, h0); unpack2(u1, l1, h1);
    unpack2(u2, l2, h2); unpack2(u3, l3, h3);
    pt[0] = fast_tanh(l0); pt[1] = fast_tanh(h0);
    pt[2] = fast_tanh(l1); pt[3] = fast_tanh(h1);
    pt[4] = fast_tanh(l2); pt[5] = fast_tanh(h2);
    pt[6] = fast_tanh(l3); pt[7] = fast_tanh(h3);
}

// Finish a group's epilogue (tanh results now long ready) into red0/red1.
__device__ __forceinline__ void epi_finish(const ull* __restrict__ sw3d, int j0,
                                           ull hx0, ull hx1, ull hx2, ull hx3,
                                           const float* pt,
                                           ull& red0, ull& red1)
{
    ull g0 = fma2(hx0, pack2(pt[0], pt[1]), hx0);
    ull g1 = fma2(hx1, pack2(pt[2], pt[3]), hx1);
    ull g2 = fma2(hx2, pack2(pt[4], pt[5]), hx2);
    ull g3 = fma2(hx3, pack2(pt[6], pt[7]), hx3);
    red0 = fma2(sw3d[j0 + 0], g0, red0);
    red1 = fma2(sw3d[j0 + 1], g1, red1);
    red0 = fma2(sw3d[j0 + 2], g2, red0);
    red1 = fma2(sw3d[j0 + 3], g3, red1);
}

__global__ __launch_bounds__(TPB, 4)
void sde_kernel(const float* __restrict__ z1,  const float* __restrict__ z2,
                const float* __restrict__ W1,  const float* __restrict__ b1,
                const float* __restrict__ W2,  const float* __restrict__ b2,
                const float* __restrict__ W3,  const float* __restrict__ b3,
                const float* __restrict__ init_log_v,
                float* __restrict__ out)
{
    // weights (warp-uniform broadcast reads); dup-pairs prebuilt for f32x2 operands
    __shared__ float sw1t[32], sb1[32];
    __shared__ ull   sw0d[32], sb2d[32], sw3d[32];
    __shared__ __align__(16) float sW2[1024];
    __shared__ float sb3s;
    // staging buffers (z in, outputs overwrite in place), 17-pad = conflict-free
    __shared__ float sza[WARPS][64][TILE + 1];   // z1 -> log_v out
    __shared__ float szb[WARPS][64][TILE + 1];   // z2 -> spot  out

    const int tid = threadIdx.x;
    for (int i = tid; i < 1024; i += TPB) sW2[i] = W2[i];
    if (tid < 32) {
        float w0 = W1[2 * tid];
        sw0d[tid] = pack2(w0, w0);
        sw1t[tid] = W1[2 * tid + 1];
        sb1[tid]  = b1[tid];
        float bb = b2[tid];
        sb2d[tid] = pack2(bb, bb);
        float w3 = W3[tid];
        sw3d[tid] = pack2(w3, w3);
    }
    if (tid == 0) sb3s = b3[0];
    __syncthreads();

    const int w = tid >> 5;
    const int l = tid & 31;
    const int pbase = blockIdx.x * (TPB * PPT) + w * 64;   // 64 paths per warp
    // thread handles paths (pbase + l) [lane A] and (pbase + l + 32) [lane B]

    const float* z1w = z1 + (size_t)pbase * N_STEPS;
    const float* z2w = z2 + (size_t)pbase * N_STEPS;
    float* out_lv = out;
    float* out_sp = out + (size_t)N_PATHS * N_STEPS;
    float* out_lq = out + 2 * (size_t)N_PATHS * N_STEPS;

    const float4* W2v = reinterpret_cast<const float4*>(sW2);

    const ull GA = pack2(0.0356774081363059f, 0.0356774081363059f);
    const ull GB = pack2(0.7978845608028654f, 0.7978845608028654f);
    const ull GH = pack2(0.5f, 0.5f);

    float lvA = init_log_v[0], lvB = lvA;
    float lsA = 0.0f, lsB = 0.0f;
    float lsqA = 0.0f, lsqB = 0.0f;

    #pragma unroll 1
    for (int s0 = 0; s0 < N_STEPS; s0 += TILE) {
        __syncwarp();
        // ---- stage z (coalesced LDG.128 -> padded smem), 64 rows x 16 cols ----
        #pragma unroll
        for (int i = 0; i < 8; i++) {
            int qi  = l + 32 * i;          // 0..255 quads
            int row = qi >> 2;
            int c0  = (qi & 3) * 4;
            float4 v1 = *reinterpret_cast<const float4*>(z1w + (size_t)row * N_STEPS + s0 + c0);
            float4 v2 = *reinterpret_cast<const float4*>(z2w + (size_t)row * N_STEPS + s0 + c0);
            sza[w][row][c0]     = v1.x; sza[w][row][c0 + 1] = v1.y;
            sza[w][row][c0 + 2] = v1.z; sza[w][row][c0 + 3] = v1.w;
            szb[w][row][c0]     = v2.x; szb[w][row][c0 + 1] = v2.y;
            szb[w][row][c0 + 2] = v2.z; szb[w][row][c0 + 3] = v2.w;
        }
        __syncwarp();

        // ---- 16 sequential SDE steps, 2 paths per thread via f32x2 ----
        #pragma unroll 1
        for (int si = 0; si < TILE; si++) {
            const int s = s0 + si;
            const float t = (float)s * INV_NSTEPS;
            const ull lvp = pack2(lvA, lvB);

            // layer 1: h1 = gelu(w0*lv + (w1*t + b1)), paired over paths.
            // 32 independent chains -> ptxas interleaves MUFU with FMA here.
            ull h1[32];
            #pragma unroll
            for (int k = 0; k < 32; k++) {
                float c1 = fmaf(sw1t[k], t, sb1[k]);       // uniform across pair
                ull arg = fma2(sw0d[k], lvp, pack2(c1, c1));
                h1[k] = gelu2(arg, GA, GB, GH);
            }

            // layer 2 + layer 3 reduction, software-pipelined across groups:
            // group jg's tanh MUFUs are issued at iteration end and consumed
            // after group jg+1's 128-cycle FMA block (MUFU latency hidden).
            ull red0 = pack2(0.0f, 0.0f);
            ull red1 = pack2(0.0f, 0.0f);
            ull a0, a1, a2, a3;
            ull hx0, hx1, hx2, hx3;
            float pt[8];

            layer2_group(W2v, sb2d, h1, 0, a0, a1, a2, a3);          // group 0 acc
            epi_issue(a0, a1, a2, a3, GA, GB, GH, hx0, hx1, hx2, hx3, pt);

            #pragma unroll 1
            for (int jg = 1; jg < 8; jg++) {
                const int j0 = jg * 4;
                layer2_group(W2v, sb2d, h1, j0, a0, a1, a2, a3);     // this group acc
                epi_finish(sw3d, j0 - 4, hx0, hx1, hx2, hx3, pt, red0, red1); // prev
                epi_issue(a0, a1, a2, a3, GA, GB, GH, hx0, hx1, hx2, hx3, pt); // this
            }
            epi_finish(sw3d, 28, hx0, hx1, hx2, hx3, pt, red0, red1); // last group

            float rA0, rB0, rA1, rB1;
            unpack2(red0, rA0, rB0);
            unpack2(red1, rA1, rB1);
            float rawA = (rA0 + rA1) + sb3s;
            float rawB = (rB0 + rB1) + sb3s;
            float lamA = LAMBDA_MAX_F * tanhf(rawA);   // accurate tanh for lambda
            float lamB = LAMBDA_MAX_F * tanhf(rawB);

            // SDE updates (scalar per path; z consumed, outputs overwrite slot)
            float zA1 = sza[w][l][si],      zA2 = szb[w][l][si];
            float zB1 = sza[w][l + 32][si], zB2 = szb[w][l + 32][si];
            float oLvA, oSpA, oLvB, oSpB;
            sde_step(lamA, zA1, zA2, lvA, lsA, lsqA, oLvA, oSpA);
            sde_step(lamB, zB1, zB2, lvB, lsB, lsqB, oLvB, oSpB);
            sza[w][l][si]      = oLvA;  szb[w][l][si]      = oSpA;
            sza[w][l + 32][si] = oLvB;  szb[w][l + 32][si] = oSpB;
        }
        __syncwarp();

        // ---- flush outputs (padded smem -> coalesced STG.128) ----
        #pragma unroll
        for (int i = 0; i < 8; i++) {
            int qi  = l + 32 * i;
            int row = qi >> 2;
            int c0  = (qi & 3) * 4;
            float4 ov, os;
            ov.x = sza[w][row][c0];     ov.y = sza[w][row][c0 + 1];
            ov.z = sza[w][row][c0 + 2]; ov.w = sza[w][row][c0 + 3];
            os.x = szb[w][row][c0];     os.y = szb[w][row][c0 + 1];
            os.z = szb[w][row][c0 + 2]; os.w = szb[w][row][c0 + 3];
            *reinterpret_cast<float4*>(out_lv + (size_t)(pbase + row) * N_STEPS + s0 + c0) = ov;
            *reinterpret_cast<float4*>(out_sp + (size_t)(pbase + row) * N_STEPS + s0 + c0) = os;
        }
    }

    out_lq[pbase + l]      = lsqA;
    out_lq[pbase + l + 32] = lsqB;
}

extern "C" void kernel_launch(void* const* d_in, const int* in_sizes, int n_in,
                              void* d_out, int out_size)
{
    (void)in_sizes; (void)n_in; (void)out_size;
    sde_kernel<<<N_PATHS / (TPB * PPT), TPB>>>(
        (const float*)d_in[0], (const float*)d_in[1],
        (const float*)d_in[2], (const float*)d_in[3],
        (const float*)d_in[4], (const float*)d_in[5],
        (const float*)d_in[6], (const float*)d_in[7],
        (const float*)d_in[8],
        (float*)d_out);
}

// round 6
// speedup vs baseline: 1.3937x; 1.3937x over previous
#include <cuda_runtime.h>

#define N_PATHS 65536
#define N_STEPS 512
#define TPB     64
#define WARPS   (TPB/32)     // 2
#define PPT     2            // paths per thread (f32x2 lanes)
#define TILE    16

// ---- constants (match reference float32 semantics) ----
#define DT_F        (1.0f/252.0f)
#define SQRT_DT_F   0.06299407883487120f     // sqrt(1/252)
#define KAPPA_F     2.72f
#define THETA_F     (-3.5f)
#define SIGMA_P_F   0.85f
#define RHO_F       (-0.85f)
#define CS_F        (0.5267826876426369f * 0.06299407883487120f) // sqrt(1-rho^2)*sqrt_dt
#define R_F         0.0373f
#define LAMBDA_MAX_F 3.0f
#define LOG_V_MIN_F (-7.0f)
#define LOG_V_MAX_F 2.0f
#define INV_NSTEPS  (1.0f/512.0f)

typedef unsigned long long ull;

// ---- packed f32x2 helpers (Blackwell fma.rn.f32x2 — ptxas won't auto-fuse) ----
__device__ __forceinline__ ull pack2(float a, float b) {
    ull r; asm("mov.b64 %0, {%1, %2};" : "=l"(r) : "f"(a), "f"(b)); return r;
}
__device__ __forceinline__ void unpack2(ull v, float& a, float& b) {
    asm("mov.b64 {%0, %1}, %2;" : "=f"(a), "=f"(b) : "l"(v));
}
__device__ __forceinline__ ull fma2(ull a, ull b, ull c) {
    ull d; asm("fma.rn.f32x2 %0, %1, %2, %3;" : "=l"(d) : "l"(a), "l"(b), "l"(c)); return d;
}
__device__ __forceinline__ ull mul2(ull a, ull b) {
    ull d; asm("mul.rn.f32x2 %0, %1, %2;" : "=l"(d) : "l"(a), "l"(b)); return d;
}

__device__ __forceinline__ float fast_tanh(float x) {
    float y;
    asm("tanh.approx.f32 %0, %1;" : "=f"(y) : "f"(x));
    return y;
}

// 5-op gelu on a pair: gelu(x) = fma(0.5x, tanh(u), 0.5x), u = x*(a*x^2+b)
// (one fewer fma-pipe op and no scalar FADDs vs the (1+tanh) form)
__device__ __forceinline__ ull gelu2(ull x, ull GA, ull GB, ull GH) {
    ull x2 = mul2(x, x);
    ull u  = mul2(x, fma2(GA, x2, GB));
    ull hx = mul2(GH, x);
    float ulo, uhi; unpack2(u, ulo, uhi);
    ull tp = pack2(fast_tanh(ulo), fast_tanh(uhi));
    return fma2(hx, tp, hx);
}

// scalar SDE update per path (identical numerics to validated R3/R4 kernels)
__device__ __forceinline__ void sde_step(float lam, float z1s, float z2s,
                                         float& lv, float& ls, float& lsq,
                                         float& o_lv, float& o_sp)
{
    float dwv = SQRT_DT_F * z1s;
    float dws = fmaf(RHO_F, dwv, CS_F * z2s);
    float mu_p    = (KAPPA_F * (THETA_F - lv)) * DT_F;
    float drift_q = mu_p - (lam * SIGMA_P_F) * DT_F;
    float lv_next = lv + drift_q + SIGMA_P_F * dwv;
    lv_next = fminf(fmaxf(lv_next, LOG_V_MIN_F), LOG_V_MAX_F);
    float ev  = __expf(lv);
    float vol = sqrtf(fmaxf(ev, 1e-10f));
    float ls_next = ls + (R_F - 0.5f * ev) * DT_F + vol * dws;
    lsq = fmaf(lam * lam, DT_F, lsq);
    o_lv = lv_next;
    o_sp = __expf(ls_next);
    lv = lv_next;
    ls = ls_next;
}

__global__ __launch_bounds__(TPB, 4)
void sde_kernel(const float* __restrict__ z1,  const float* __restrict__ z2,
                const float* __restrict__ W1,  const float* __restrict__ b1,
                const float* __restrict__ W2,  const float* __restrict__ b2,
                const float* __restrict__ W3,  const float* __restrict__ b3,
                const float* __restrict__ init_log_v,
                float* __restrict__ out)
{
    // weights (warp-uniform broadcast reads); dup-pairs prebuilt for f32x2 operands
    __shared__ float sw1t[32], sb1[32];
    __shared__ ull   sw0d[32], sb2d[32], sw3d[32];
    __shared__ __align__(16) float sW2[1024];
    __shared__ float sb3s;
    // staging buffers (z in, outputs overwrite in place), 17-pad = conflict-free
    __shared__ float sza[WARPS][64][TILE + 1];   // z1 -> log_v out
    __shared__ float szb[WARPS][64][TILE + 1];   // z2 -> spot  out

    const int tid = threadIdx.x;
    for (int i = tid; i < 1024; i += TPB) sW2[i] = W2[i];
    if (tid < 32) {
        float w0 = W1[2 * tid];
        sw0d[tid] = pack2(w0, w0);
        sw1t[tid] = W1[2 * tid + 1];
        sb1[tid]  = b1[tid];
        float bb = b2[tid];
        sb2d[tid] = pack2(bb, bb);
        float w3 = W3[tid];
        sw3d[tid] = pack2(w3, w3);
    }
    if (tid == 0) sb3s = b3[0];
    __syncthreads();

    const int w = tid >> 5;
    const int l = tid & 31;
    const int pbase = blockIdx.x * (TPB * PPT) + w * 64;   // 64 paths per warp
    // thread handles paths (pbase + l) [lane A] and (pbase + l + 32) [lane B]

    const float* z1w = z1 + (size_t)pbase * N_STEPS;
    const float* z2w = z2 + (size_t)pbase * N_STEPS;
    float* out_lv = out;
    float* out_sp = out + (size_t)N_PATHS * N_STEPS;
    float* out_lq = out + 2 * (size_t)N_PATHS * N_STEPS;

    const float4* W2v = reinterpret_cast<const float4*>(sW2);

    const ull GA = pack2(0.0356774081363059f, 0.0356774081363059f);
    const ull GB = pack2(0.7978845608028654f, 0.7978845608028654f);
    const ull GH = pack2(0.5f, 0.5f);

    float lvA = init_log_v[0], lvB = lvA;
    float lsA = 0.0f, lsB = 0.0f;
    float lsqA = 0.0f, lsqB = 0.0f;

    #pragma unroll 1
    for (int s0 = 0; s0 < N_STEPS; s0 += TILE) {
        __syncwarp();
        // ---- stage z (coalesced LDG.128 -> padded smem), 64 rows x 16 cols ----
        #pragma unroll
        for (int i = 0; i < 8; i++) {
            int qi  = l + 32 * i;          // 0..255 quads
            int row = qi >> 2;
            int c0  = (qi & 3) * 4;
            float4 v1 = *reinterpret_cast<const float4*>(z1w + (size_t)row * N_STEPS + s0 + c0);
            float4 v2 = *reinterpret_cast<const float4*>(z2w + (size_t)row * N_STEPS + s0 + c0);
            sza[w][row][c0]     = v1.x; sza[w][row][c0 + 1] = v1.y;
            sza[w][row][c0 + 2] = v1.z; sza[w][row][c0 + 3] = v1.w;
            szb[w][row][c0]     = v2.x; szb[w][row][c0 + 1] = v2.y;
            szb[w][row][c0 + 2] = v2.z; szb[w][row][c0 + 3] = v2.w;
        }
        __syncwarp();

        // ---- 16 sequential SDE steps, 2 paths per thread via f32x2 ----
        #pragma unroll 1
        for (int si = 0; si < TILE; si++) {
            const int s = s0 + si;
            const float t = (float)s * INV_NSTEPS;
            const ull lvp = pack2(lvA, lvB);

            // layer 1: h1 = gelu(w0*lv + (w1*t + b1)), paired over paths
            ull h1[32];
            #pragma unroll
            for (int k = 0; k < 32; k++) {
                float c1 = fmaf(sw1t[k], t, sb1[k]);       // uniform across pair
                ull arg = fma2(sw0d[k], lvp, pack2(c1, c1));
                h1[k] = gelu2(arg, GA, GB, GH);
            }

            // layer 2 + layer 3 reduction. 8 groups of 4 neurons (unroll 1 ->
            // small live set). Each weight: 1 dup-pack + 1 FFMA2 serving both
            // paths. Weight quad loads shared across the pair.
            ull red0 = pack2(0.0f, 0.0f);
            ull red1 = pack2(0.0f, 0.0f);
            #pragma unroll 1
            for (int jg = 0; jg < 8; jg++) {
                const int j0 = jg * 4;
                ull a0 = sb2d[j0 + 0];
                ull a1 = sb2d[j0 + 1];
                ull a2 = sb2d[j0 + 2];
                ull a3 = sb2d[j0 + 3];
                #pragma unroll
                for (int k4 = 0; k4 < 8; k4++) {
                    ull h0 = h1[4 * k4 + 0];
                    ull hA = h1[4 * k4 + 1];
                    ull hB = h1[4 * k4 + 2];
                    ull hC = h1[4 * k4 + 3];
                    float4 q0 = W2v[(j0 + 0) * 8 + k4];
                    float4 q1 = W2v[(j0 + 1) * 8 + k4];
                    float4 q2 = W2v[(j0 + 2) * 8 + k4];
                    float4 q3 = W2v[(j0 + 3) * 8 + k4];
                    a0 = fma2(pack2(q0.x, q0.x), h0, a0);
                    a0 = fma2(pack2(q0.y, q0.y), hA, a0);
                    a0 = fma2(pack2(q0.z, q0.z), hB, a0);
                    a0 = fma2(pack2(q0.w, q0.w), hC, a0);
                    a1 = fma2(pack2(q1.x, q1.x), h0, a1);
                    a1 = fma2(pack2(q1.y, q1.y), hA, a1);
                    a1 = fma2(pack2(q1.z, q1.z), hB, a1);
                    a1 = fma2(pack2(q1.w, q1.w), hC, a1);
                    a2 = fma2(pack2(q2.x, q2.x), h0, a2);
                    a2 = fma2(pack2(q2.y, q2.y), hA, a2);
                    a2 = fma2(pack2(q2.z, q2.z), hB, a2);
                    a2 = fma2(pack2(q2.w, q2.w), hC, a2);
                    a3 = fma2(pack2(q3.x, q3.x), h0, a3);
                    a3 = fma2(pack2(q3.y, q3.y), hA, a3);
                    a3 = fma2(pack2(q3.z, q3.z), hB, a3);
                    a3 = fma2(pack2(q3.w, q3.w), hC, a3);
                }
                red0 = fma2(sw3d[j0 + 0], gelu2(a0, GA, GB, GH), red0);
                red1 = fma2(sw3d[j0 + 1], gelu2(a1, GA, GB, GH), red1);
                red0 = fma2(sw3d[j0 + 2], gelu2(a2, GA, GB, GH), red0);
                red1 = fma2(sw3d[j0 + 3], gelu2(a3, GA, GB, GH), red1);
            }
            float rA0, rB0, rA1, rB1;
            unpack2(red0, rA0, rB0);
            unpack2(red1, rA1, rB1);
            float rawA = (rA0 + rA1) + sb3s;
            float rawB = (rB0 + rB1) + sb3s;
            float lamA = LAMBDA_MAX_F * tanhf(rawA);   // accurate tanh for lambda
            float lamB = LAMBDA_MAX_F * tanhf(rawB);

            // SDE updates (scalar per path; z consumed, outputs overwrite slot)
            float zA1 = sza[w][l][si],      zA2 = szb[w][l][si];
            float zB1 = sza[w][l + 32][si], zB2 = szb[w][l + 32][si];
            float oLvA, oSpA, oLvB, oSpB;
            sde_step(lamA, zA1, zA2, lvA, lsA, lsqA, oLvA, oSpA);
            sde_step(lamB, zB1, zB2, lvB, lsB, lsqB, oLvB, oSpB);
            sza[w][l][si]      = oLvA;  szb[w][l][si]      = oSpA;
            sza[w][l + 32][si] = oLvB;  szb[w][l + 32][si] = oSpB;
        }
        __syncwarp();

        // ---- flush outputs (padded smem -> coalesced STG.128) ----
        #pragma unroll
        for (int i = 0; i < 8; i++) {
            int qi  = l + 32 * i;
            int row = qi >> 2;
            int c0  = (qi & 3) * 4;
            float4 ov, os;
            ov.x = sza[w][row][c0];     ov.y = sza[w][row][c0 + 1];
            ov.z = sza[w][row][c0 + 2]; ov.w = sza[w][row][c0 + 3];
            os.x = szb[w][row][c0];     os.y = szb[w][row][c0 + 1];
            os.z = szb[w][row][c0 + 2]; os.w = szb[w][row][c0 + 3];
            *reinterpret_cast<float4*>(out_lv + (size_t)(pbase + row) * N_STEPS + s0 + c0) = ov;
            *reinterpret_cast<float4*>(out_sp + (size_t)(pbase + row) * N_STEPS + s0 + c0) = os;
        }
    }

    out_lq[pbase + l]      = lsqA;
    out_lq[pbase + l + 32] = lsqB;
}

extern "C" void kernel_launch(void* const* d_in, const int* in_sizes, int n_in,
                              void* d_out, int out_size)
{
    (void)in_sizes; (void)n_in; (void)out_size;
    sde_kernel<<<N_PATHS / (TPB * PPT), TPB>>>(
        (const float*)d_in[0], (const float*)d_in[1],
        (const float*)d_in[2], (const float*)d_in[3],
        (const float*)d_in[4], (const float*)d_in[5],
        (const float*)d_in[6], (const float*)d_in[7],
        (const float*)d_in[8],
        (float*)d_out);
}

// round 7
// speedup vs baseline: 6.9458x; 4.9838x over previous
#include <cuda_runtime.h>

#define N_PATHS 65536
#define N_STEPS 512
#define NPTS    4096
#define HALF_NPTS (NPTS/2)
#define TILE    16

// phase-1 (table build) config
#define TPB1    128
// phase-2 (SDE sweep) config
#define TPB2    128
#define WARPS2  (TPB2/32)

// ---- constants (match reference float32 semantics) ----
#define DT_F        (1.0f/252.0f)
#define SQRT_DT_F   0.06299407883487120f     // sqrt(1/252)
#define KAPPA_F     2.72f
#define THETA_F     (-3.5f)
#define SIGMA_P_F   0.85f
#define RHO_F       (-0.85f)
#define CS_F        (0.5267826876426369f * 0.06299407883487120f) // sqrt(1-rho^2)*sqrt_dt
#define R_F         0.0373f
#define LAMBDA_MAX_F 3.0f
#define LOG_V_MIN_F (-7.0f)
#define LOG_V_MAX_F 2.0f
#define INV_NSTEPS  (1.0f/512.0f)
#define TAB_H       ((LOG_V_MAX_F - LOG_V_MIN_F) / (float)(NPTS - 1))
#define TAB_SCALE   ((float)(NPTS - 1) / (LOG_V_MAX_F - LOG_V_MIN_F))

// lambda lookup table: [N_STEPS][NPTS], built by tab_kernel (device global = legal scratch)
__device__ float g_lam_tab[N_STEPS * NPTS];

typedef unsigned long long ull;

// ---- packed f32x2 helpers (Blackwell fma.rn.f32x2) ----
__device__ __forceinline__ ull pack2(float a, float b) {
    ull r; asm("mov.b64 %0, {%1, %2};" : "=l"(r) : "f"(a), "f"(b)); return r;
}
__device__ __forceinline__ void unpack2(ull v, float& a, float& b) {
    asm("mov.b64 {%0, %1}, %2;" : "=f"(a), "=f"(b) : "l"(v));
}
__device__ __forceinline__ ull fma2(ull a, ull b, ull c) {
    ull d; asm("fma.rn.f32x2 %0, %1, %2, %3;" : "=l"(d) : "l"(a), "l"(b), "l"(c)); return d;
}
__device__ __forceinline__ ull mul2(ull a, ull b) {
    ull d; asm("mul.rn.f32x2 %0, %1, %2;" : "=l"(d) : "l"(a), "l"(b)); return d;
}

__device__ __forceinline__ float fast_tanh(float x) {
    float y;
    asm("tanh.approx.f32 %0, %1;" : "=f"(y) : "f"(x));
    return y;
}

// 5-op gelu on a pair (validated in R4/R6): gelu(x)=fma(0.5x, tanh(u), 0.5x)
__device__ __forceinline__ ull gelu2(ull x, ull GA, ull GB, ull GH) {
    ull x2 = mul2(x, x);
    ull u  = mul2(x, fma2(GA, x2, GB));
    ull hx = mul2(GH, x);
    float ulo, uhi; unpack2(u, ulo, uhi);
    ull tp = pack2(fast_tanh(ulo), fast_tanh(uhi));
    return fma2(hx, tp, hx);
}

// ============================================================================
// Phase 1: build lambda table. One thread computes the MLP at 2 grid points
// (f32x2 lanes) for one time step. Exact same pair-MLP code validated in R4/R6.
// ============================================================================
__global__ __launch_bounds__(TPB1, 4)
void tab_kernel(const float* __restrict__ W1,  const float* __restrict__ b1,
                const float* __restrict__ W2,  const float* __restrict__ b2,
                const float* __restrict__ W3,  const float* __restrict__ b3)
{
    __shared__ float sw1t[32], sb1[32];
    __shared__ ull   sw0d[32], sb2d[32], sw3d[32];
    __shared__ __align__(16) float sW2[1024];
    __shared__ float sb3s;

    const int tid = threadIdx.x;
    for (int i = tid; i < 1024; i += TPB1) sW2[i] = W2[i];
    if (tid < 32) {
        float w0 = W1[2 * tid];
        sw0d[tid] = pack2(w0, w0);
        sw1t[tid] = W1[2 * tid + 1];
        sb1[tid]  = b1[tid];
        float bb = b2[tid];
        sb2d[tid] = pack2(bb, bb);
        float w3 = W3[tid];
        sw3d[tid] = pack2(w3, w3);
    }
    if (tid == 0) sb3s = b3[0];
    __syncthreads();

    const float4* W2v = reinterpret_cast<const float4*>(sW2);
    const ull GA = pack2(0.0356774081363059f, 0.0356774081363059f);
    const ull GB = pack2(0.7978845608028654f, 0.7978845608028654f);
    const ull GH = pack2(0.5f, 0.5f);

    const int gid = blockIdx.x * TPB1 + tid;       // 0 .. N_STEPS*HALF_NPTS-1
    const int s   = gid >> 11;                     // / HALF_NPTS (2048)
    const int r   = gid & (HALF_NPTS - 1);
    const float t = (float)s * INV_NSTEPS;

    const float lvA = LOG_V_MIN_F + (float)r * TAB_H;
    const float lvB = LOG_V_MIN_F + (float)(r + HALF_NPTS) * TAB_H;
    const ull lvp = pack2(lvA, lvB);

    // layer 1
    ull h1[32];
    #pragma unroll
    for (int k = 0; k < 32; k++) {
        float c1 = fmaf(sw1t[k], t, sb1[k]);
        ull arg = fma2(sw0d[k], lvp, pack2(c1, c1));
        h1[k] = gelu2(arg, GA, GB, GH);
    }

    // layer 2 + layer 3 reduction (8 groups of 4 neurons, validated structure)
    ull red0 = pack2(0.0f, 0.0f);
    ull red1 = pack2(0.0f, 0.0f);
    #pragma unroll 1
    for (int jg = 0; jg < 8; jg++) {
        const int j0 = jg * 4;
        ull a0 = sb2d[j0 + 0];
        ull a1 = sb2d[j0 + 1];
        ull a2 = sb2d[j0 + 2];
        ull a3 = sb2d[j0 + 3];
        #pragma unroll
        for (int k4 = 0; k4 < 8; k4++) {
            ull h0 = h1[4 * k4 + 0];
            ull hA = h1[4 * k4 + 1];
            ull hB = h1[4 * k4 + 2];
            ull hC = h1[4 * k4 + 3];
            float4 q0 = W2v[(j0 + 0) * 8 + k4];
            float4 q1 = W2v[(j0 + 1) * 8 + k4];
            float4 q2 = W2v[(j0 + 2) * 8 + k4];
            float4 q3 = W2v[(j0 + 3) * 8 + k4];
            a0 = fma2(pack2(q0.x, q0.x), h0, a0);
            a0 = fma2(pack2(q0.y, q0.y), hA, a0);
            a0 = fma2(pack2(q0.z, q0.z), hB, a0);
            a0 = fma2(pack2(q0.w, q0.w), hC, a0);
            a1 = fma2(pack2(q1.x, q1.x), h0, a1);
            a1 = fma2(pack2(q1.y, q1.y), hA, a1);
            a1 = fma2(pack2(q1.z, q1.z), hB, a1);
            a1 = fma2(pack2(q1.w, q1.w), hC, a1);
            a2 = fma2(pack2(q2.x, q2.x), h0, a2);
            a2 = fma2(pack2(q2.y, q2.y), hA, a2);
            a2 = fma2(pack2(q2.z, q2.z), hB, a2);
            a2 = fma2(pack2(q2.w, q2.w), hC, a2);
            a3 = fma2(pack2(q3.x, q3.x), h0, a3);
            a3 = fma2(pack2(q3.y, q3.y), hA, a3);
            a3 = fma2(pack2(q3.z, q3.z), hB, a3);
            a3 = fma2(pack2(q3.w, q3.w), hC, a3);
        }
        red0 = fma2(sw3d[j0 + 0], gelu2(a0, GA, GB, GH), red0);
        red1 = fma2(sw3d[j0 + 1], gelu2(a1, GA, GB, GH), red1);
        red0 = fma2(sw3d[j0 + 2], gelu2(a2, GA, GB, GH), red0);
        red1 = fma2(sw3d[j0 + 3], gelu2(a3, GA, GB, GH), red1);
    }
    float rA0, rB0, rA1, rB1;
    unpack2(red0, rA0, rB0);
    unpack2(red1, rA1, rB1);
    float rawA = (rA0 + rA1) + sb3s;
    float rawB = (rB0 + rB1) + sb3s;

    g_lam_tab[s * NPTS + r]             = LAMBDA_MAX_F * tanhf(rawA);
    g_lam_tab[s * NPTS + r + HALF_NPTS] = LAMBDA_MAX_F * tanhf(rawB);
}

// ============================================================================
// Phase 2: SDE sweep, MLP replaced by table lerp. R3 staging skeleton
// (coalesced LDG.128 -> padded smem tiles, coalesced STG.128 out).
// ============================================================================
__global__ __launch_bounds__(TPB2, 4)
void sde_kernel(const float* __restrict__ z1, const float* __restrict__ z2,
                const float* __restrict__ init_log_v,
                float* __restrict__ out)
{
    __shared__ float sz1[WARPS2][32][TILE + 1];
    __shared__ float sz2[WARPS2][32][TILE + 1];
    __shared__ float sov[WARPS2][32][TILE + 1];
    __shared__ float sos[WARPS2][32][TILE + 1];

    const int tid = threadIdx.x;
    const int w = tid >> 5;
    const int l = tid & 31;
    const int pbase = blockIdx.x * TPB2 + w * 32;

    const float* z1w = z1 + (size_t)pbase * N_STEPS;
    const float* z2w = z2 + (size_t)pbase * N_STEPS;
    float* out_lv = out;
    float* out_sp = out + (size_t)N_PATHS * N_STEPS;
    float* out_lq = out + 2 * (size_t)N_PATHS * N_STEPS;

    float lv  = init_log_v[0];
    float ls  = 0.0f;
    float lsq = 0.0f;

    const int pl_lo = (l >> 2);
    const int so    = (l & 3) * 4;

    #pragma unroll 1
    for (int s0 = 0; s0 < N_STEPS; s0 += TILE) {
        __syncwarp();
        #pragma unroll
        for (int it = 0; it < 4; it++) {
            int pl = it * 8 + pl_lo;
            float4 v1 = *reinterpret_cast<const float4*>(z1w + (size_t)pl * N_STEPS + s0 + so);
            float4 v2 = *reinterpret_cast<const float4*>(z2w + (size_t)pl * N_STEPS + s0 + so);
            sz1[w][pl][so]     = v1.x; sz1[w][pl][so + 1] = v1.y;
            sz1[w][pl][so + 2] = v1.z; sz1[w][pl][so + 3] = v1.w;
            sz2[w][pl][so]     = v2.x; sz2[w][pl][so + 1] = v2.y;
            sz2[w][pl][so + 2] = v2.z; sz2[w][pl][so + 3] = v2.w;
        }
        __syncwarp();

        #pragma unroll 1
        for (int si = 0; si < TILE; si++) {
            const int s = s0 + si;

            // lambda via table lerp: lv in [-7,2] guaranteed by the clip
            float x = (lv - LOG_V_MIN_F) * TAB_SCALE;
            int   i = (int)x;
            i = (i > NPTS - 2) ? (NPTS - 2) : i;
            float fr = x - (float)i;
            const float* trow = g_lam_tab + (size_t)s * NPTS;
            float t0 = __ldg(trow + i);
            float t1 = __ldg(trow + i + 1);
            float lam = fmaf(fr, t1 - t0, t0);

            // SDE update (identical numerics to validated kernels)
            float z1s = sz1[w][l][si];
            float z2s = sz2[w][l][si];
            float dwv = SQRT_DT_F * z1s;
            float dws = fmaf(RHO_F, dwv, CS_F * z2s);

            float mu_p    = (KAPPA_F * (THETA_F - lv)) * DT_F;
            float drift_q = mu_p - (lam * SIGMA_P_F) * DT_F;
            float lv_next = lv + drift_q + SIGMA_P_F * dwv;
            lv_next = fminf(fmaxf(lv_next, LOG_V_MIN_F), LOG_V_MAX_F);

            float ev  = __expf(lv);
            float vol = sqrtf(fmaxf(ev, 1e-10f));
            float ls_next = ls + (R_F - 0.5f * ev) * DT_F + vol * dws;

            lsq = fmaf(lam * lam, DT_F, lsq);

            sov[w][l][si] = lv_next;
            sos[w][l][si] = __expf(ls_next);

            lv = lv_next;
            ls = ls_next;
        }
        __syncwarp();

        #pragma unroll
        for (int it = 0; it < 4; it++) {
            int pl = it * 8 + pl_lo;
            float4 ov, os;
            ov.x = sov[w][pl][so];     ov.y = sov[w][pl][so + 1];
            ov.z = sov[w][pl][so + 2]; ov.w = sov[w][pl][so + 3];
            os.x = sos[w][pl][so];     os.y = sos[w][pl][so + 1];
            os.z = sos[w][pl][so + 2]; os.w = sos[w][pl][so + 3];
            *reinterpret_cast<float4*>(out_lv + (size_t)(pbase + pl) * N_STEPS + s0 + so) = ov;
            *reinterpret_cast<float4*>(out_sp + (size_t)(pbase + pl) * N_STEPS + s0 + so) = os;
        }
    }

    out_lq[pbase + l] = lsq;
}

extern "C" void kernel_launch(void* const* d_in, const int* in_sizes, int n_in,
                              void* d_out, int out_size)
{
    (void)in_sizes; (void)n_in; (void)out_size;
    // Phase 1: build lambda(lv, t) table — 512 steps x 4096 grid points
    tab_kernel<<<(N_STEPS * HALF_NPTS) / TPB1, TPB1>>>(
        (const float*)d_in[2], (const float*)d_in[3],
        (const float*)d_in[4], (const float*)d_in[5],
        (const float*)d_in[6], (const float*)d_in[7]);
    // Phase 2: SDE sweep with table-interpolated lambda
    sde_kernel<<<N_PATHS / TPB2, TPB2>>>(
        (const float*)d_in[0], (const float*)d_in[1],
        (const float*)d_in[8],
        (float*)d_out);
}

// round 8
// speedup vs baseline: 10.0669x; 1.4493x over previous
#include <cuda_runtime.h>

#define N_PATHS 65536
#define N_STEPS 512

// table resolution (per time step) and phase-2 tiling
#define NPTS    512
#define HALF_NPTS (NPTS/2)
#define TILE    8

// phase-1 (table build) config
#define TPB1    128
// phase-2 (SDE sweep) config
#define TPB2    128
#define WARPS2  (TPB2/32)

// ---- constants (match reference float32 semantics) ----
#define DT_F        (1.0f/252.0f)
#define SQRT_DT_F   0.06299407883487120f     // sqrt(1/252)
#define KAPPA_F     2.72f
#define THETA_F     (-3.5f)
#define SIGMA_P_F   0.85f
#define RHO_F       (-0.85f)
#define CS_F        (0.5267826876426369f * 0.06299407883487120f) // sqrt(1-rho^2)*sqrt_dt
#define R_F         0.0373f
#define LAMBDA_MAX_F 3.0f
#define LOG_V_MIN_F (-7.0f)
#define LOG_V_MAX_F 2.0f
#define INV_NSTEPS  (1.0f/512.0f)
#define TAB_H       ((LOG_V_MAX_F - LOG_V_MIN_F) / (float)(NPTS - 1))
#define TAB_SCALE   ((float)(NPTS - 1) / (LOG_V_MAX_F - LOG_V_MIN_F))

// lambda lookup table: [N_STEPS][NPTS], built by tab_kernel (device global = legal scratch)
__device__ float g_lam_tab[N_STEPS * NPTS];

typedef unsigned long long ull;

// ---- packed f32x2 helpers (Blackwell fma.rn.f32x2) ----
__device__ __forceinline__ ull pack2(float a, float b) {
    ull r; asm("mov.b64 %0, {%1, %2};" : "=l"(r) : "f"(a), "f"(b)); return r;
}
__device__ __forceinline__ void unpack2(ull v, float& a, float& b) {
    asm("mov.b64 {%0, %1}, %2;" : "=f"(a), "=f"(b) : "l"(v));
}
__device__ __forceinline__ ull fma2(ull a, ull b, ull c) {
    ull d; asm("fma.rn.f32x2 %0, %1, %2, %3;" : "=l"(d) : "l"(a), "l"(b), "l"(c)); return d;
}
__device__ __forceinline__ ull mul2(ull a, ull b) {
    ull d; asm("mul.rn.f32x2 %0, %1, %2;" : "=l"(d) : "l"(a), "l"(b)); return d;
}

__device__ __forceinline__ float fast_tanh(float x) {
    float y;
    asm("tanh.approx.f32 %0, %1;" : "=f"(y) : "f"(x));
    return y;
}

// 5-op gelu on a pair (validated): gelu(x)=fma(0.5x, tanh(u), 0.5x)
__device__ __forceinline__ ull gelu2(ull x, ull GA, ull GB, ull GH) {
    ull x2 = mul2(x, x);
    ull u  = mul2(x, fma2(GA, x2, GB));
    ull hx = mul2(GH, x);
    float ulo, uhi; unpack2(u, ulo, uhi);
    ull tp = pack2(fast_tanh(ulo), fast_tanh(uhi));
    return fma2(hx, tp, hx);
}

// ============================================================================
// Phase 1: build lambda table. One thread = MLP at 2 grid points (f32x2 lanes)
// for one time step. Same pair-MLP code validated in R4/R6/R7.
// ============================================================================
__global__ __launch_bounds__(TPB1, 4)
void tab_kernel(const float* __restrict__ W1,  const float* __restrict__ b1,
                const float* __restrict__ W2,  const float* __restrict__ b2,
                const float* __restrict__ W3,  const float* __restrict__ b3)
{
    __shared__ float sw1t[32], sb1[32];
    __shared__ ull   sw0d[32], sb2d[32], sw3d[32];
    __shared__ __align__(16) float sW2[1024];
    __shared__ float sb3s;

    const int tid = threadIdx.x;
    for (int i = tid; i < 1024; i += TPB1) sW2[i] = W2[i];
    if (tid < 32) {
        float w0 = W1[2 * tid];
        sw0d[tid] = pack2(w0, w0);
        sw1t[tid] = W1[2 * tid + 1];
        sb1[tid]  = b1[tid];
        float bb = b2[tid];
        sb2d[tid] = pack2(bb, bb);
        float w3 = W3[tid];
        sw3d[tid] = pack2(w3, w3);
    }
    if (tid == 0) sb3s = b3[0];
    __syncthreads();

    const float4* W2v = reinterpret_cast<const float4*>(sW2);
    const ull GA = pack2(0.0356774081363059f, 0.0356774081363059f);
    const ull GB = pack2(0.7978845608028654f, 0.7978845608028654f);
    const ull GH = pack2(0.5f, 0.5f);

    const int gid = blockIdx.x * TPB1 + tid;       // 0 .. N_STEPS*HALF_NPTS-1
    const int s   = gid >> 8;                      // / HALF_NPTS (256)
    const int r   = gid & (HALF_NPTS - 1);
    const float t = (float)s * INV_NSTEPS;

    const float lvA = LOG_V_MIN_F + (float)r * TAB_H;
    const float lvB = LOG_V_MIN_F + (float)(r + HALF_NPTS) * TAB_H;
    const ull lvp = pack2(lvA, lvB);

    // layer 1
    ull h1[32];
    #pragma unroll
    for (int k = 0; k < 32; k++) {
        float c1 = fmaf(sw1t[k], t, sb1[k]);
        ull arg = fma2(sw0d[k], lvp, pack2(c1, c1));
        h1[k] = gelu2(arg, GA, GB, GH);
    }

    // layer 2 + layer 3 reduction (8 groups of 4 neurons, validated structure)
    ull red0 = pack2(0.0f, 0.0f);
    ull red1 = pack2(0.0f, 0.0f);
    #pragma unroll 1
    for (int jg = 0; jg < 8; jg++) {
        const int j0 = jg * 4;
        ull a0 = sb2d[j0 + 0];
        ull a1 = sb2d[j0 + 1];
        ull a2 = sb2d[j0 + 2];
        ull a3 = sb2d[j0 + 3];
        #pragma unroll
        for (int k4 = 0; k4 < 8; k4++) {
            ull h0 = h1[4 * k4 + 0];
            ull hA = h1[4 * k4 + 1];
            ull hB = h1[4 * k4 + 2];
            ull hC = h1[4 * k4 + 3];
            float4 q0 = W2v[(j0 + 0) * 8 + k4];
            float4 q1 = W2v[(j0 + 1) * 8 + k4];
            float4 q2 = W2v[(j0 + 2) * 8 + k4];
            float4 q3 = W2v[(j0 + 3) * 8 + k4];
            a0 = fma2(pack2(q0.x, q0.x), h0, a0);
            a0 = fma2(pack2(q0.y, q0.y), hA, a0);
            a0 = fma2(pack2(q0.z, q0.z), hB, a0);
            a0 = fma2(pack2(q0.w, q0.w), hC, a0);
            a1 = fma2(pack2(q1.x, q1.x), h0, a1);
            a1 = fma2(pack2(q1.y, q1.y), hA, a1);
            a1 = fma2(pack2(q1.z, q1.z), hB, a1);
            a1 = fma2(pack2(q1.w, q1.w), hC, a1);
            a2 = fma2(pack2(q2.x, q2.x), h0, a2);
            a2 = fma2(pack2(q2.y, q2.y), hA, a2);
            a2 = fma2(pack2(q2.z, q2.z), hB, a2);
            a2 = fma2(pack2(q2.w, q2.w), hC, a2);
            a3 = fma2(pack2(q3.x, q3.x), h0, a3);
            a3 = fma2(pack2(q3.y, q3.y), hA, a3);
            a3 = fma2(pack2(q3.z, q3.z), hB, a3);
            a3 = fma2(pack2(q3.w, q3.w), hC, a3);
        }
        red0 = fma2(sw3d[j0 + 0], gelu2(a0, GA, GB, GH), red0);
        red1 = fma2(sw3d[j0 + 1], gelu2(a1, GA, GB, GH), red1);
        red0 = fma2(sw3d[j0 + 2], gelu2(a2, GA, GB, GH), red0);
        red1 = fma2(sw3d[j0 + 3], gelu2(a3, GA, GB, GH), red1);
    }
    float rA0, rB0, rA1, rB1;
    unpack2(red0, rA0, rB0);
    unpack2(red1, rA1, rB1);
    float rawA = (rA0 + rA1) + sb3s;
    float rawB = (rB0 + rB1) + sb3s;

    g_lam_tab[s * NPTS + r]             = LAMBDA_MAX_F * tanhf(rawA);
    g_lam_tab[s * NPTS + r + HALF_NPTS] = LAMBDA_MAX_F * tanhf(rawB);
}

// ============================================================================
// Phase 2: SDE sweep. Lambda lerp now gathers from a SHARED-MEMORY table tile
// (8 steps x 512 pts = 16KB) refilled cooperatively per tile — kills the
// L1tex wavefront storm of divergent global gathers.
// ============================================================================
__global__ __launch_bounds__(TPB2, 4)
void sde_kernel(const float* __restrict__ z1, const float* __restrict__ z2,
                const float* __restrict__ init_log_v,
                float* __restrict__ out)
{
    __shared__ float sz1[WARPS2][32][TILE + 1];
    __shared__ float sz2[WARPS2][32][TILE + 1];
    __shared__ float sov[WARPS2][32][TILE + 1];
    __shared__ float sos[WARPS2][32][TILE + 1];
    __shared__ __align__(16) float stab[TILE][NPTS];   // 16 KB lambda tile

    const int tid = threadIdx.x;
    const int w = tid >> 5;
    const int l = tid & 31;
    const int pbase = blockIdx.x * TPB2 + w * 32;

    const float* z1w = z1 + (size_t)pbase * N_STEPS;
    const float* z2w = z2 + (size_t)pbase * N_STEPS;
    float* out_lv = out;
    float* out_sp = out + (size_t)N_PATHS * N_STEPS;
    float* out_lq = out + 2 * (size_t)N_PATHS * N_STEPS;

    float lv  = init_log_v[0];
    float ls  = 0.0f;
    float lsq = 0.0f;

    const int pl_lo = (l >> 1);        // 0..15 (2 quads per 8-step row)
    const int so    = (l & 1) * 4;     // 0 or 4

    #pragma unroll 1
    for (int s0 = 0; s0 < N_STEPS; s0 += TILE) {
        __syncthreads();   // previous tile's stab reads complete

        // ---- refill lambda tile: 8 rows x 512 = 4096 floats, coalesced ----
        {
            const float4* src = reinterpret_cast<const float4*>(g_lam_tab + (size_t)s0 * NPTS);
            float4* dst = reinterpret_cast<float4*>(&stab[0][0]);
            #pragma unroll
            for (int i = 0; i < (TILE * NPTS / 4) / TPB2; i++)   // 8 iters
                dst[tid + i * TPB2] = src[tid + i * TPB2];
        }

        // ---- stage z (coalesced LDG.128 -> padded smem), 32 rows x 8 cols ----
        #pragma unroll
        for (int it = 0; it < 2; it++) {
            int pl = it * 16 + pl_lo;
            float4 v1 = *reinterpret_cast<const float4*>(z1w + (size_t)pl * N_STEPS + s0 + so);
            float4 v2 = *reinterpret_cast<const float4*>(z2w + (size_t)pl * N_STEPS + s0 + so);
            sz1[w][pl][so]     = v1.x; sz1[w][pl][so + 1] = v1.y;
            sz1[w][pl][so + 2] = v1.z; sz1[w][pl][so + 3] = v1.w;
            sz2[w][pl][so]     = v2.x; sz2[w][pl][so + 1] = v2.y;
            sz2[w][pl][so + 2] = v2.z; sz2[w][pl][so + 3] = v2.w;
        }
        __syncthreads();   // stab + z tiles visible to all

        // ---- 8 sequential SDE steps ----
        #pragma unroll 1
        for (int si = 0; si < TILE; si++) {
            // lambda via smem table lerp: lv in [-7,2] guaranteed by the clip
            float x = (lv - LOG_V_MIN_F) * TAB_SCALE;
            int   i = (int)x;
            i = (i > NPTS - 2) ? (NPTS - 2) : i;
            float fr = x - (float)i;
            float t0 = stab[si][i];
            float t1 = stab[si][i + 1];
            float lam = fmaf(fr, t1 - t0, t0);

            // SDE update (identical numerics to validated kernels)
            float z1s = sz1[w][l][si];
            float z2s = sz2[w][l][si];
            float dwv = SQRT_DT_F * z1s;
            float dws = fmaf(RHO_F, dwv, CS_F * z2s);

            float mu_p    = (KAPPA_F * (THETA_F - lv)) * DT_F;
            float drift_q = mu_p - (lam * SIGMA_P_F) * DT_F;
            float lv_next = lv + drift_q + SIGMA_P_F * dwv;
            lv_next = fminf(fmaxf(lv_next, LOG_V_MIN_F), LOG_V_MAX_F);

            float ev  = __expf(lv);
            float vol = sqrtf(fmaxf(ev, 1e-10f));
            float ls_next = ls + (R_F - 0.5f * ev) * DT_F + vol * dws;

            lsq = fmaf(lam * lam, DT_F, lsq);

            sov[w][l][si] = lv_next;
            sos[w][l][si] = __expf(ls_next);

            lv = lv_next;
            ls = ls_next;
        }
        __syncwarp();   // sov/sos writes visible within the warp before flush

        // ---- flush outputs (padded smem -> coalesced STG.128) ----
        #pragma unroll
        for (int it = 0; it < 2; it++) {
            int pl = it * 16 + pl_lo;
            float4 ov, os;
            ov.x = sov[w][pl][so];     ov.y = sov[w][pl][so + 1];
            ov.z = sov[w][pl][so + 2]; ov.w = sov[w][pl][so + 3];
            os.x = sos[w][pl][so];     os.y = sos[w][pl][so + 1];
            os.z = sos[w][pl][so + 2]; os.w = sos[w][pl][so + 3];
            *reinterpret_cast<float4*>(out_lv + (size_t)(pbase + pl) * N_STEPS + s0 + so) = ov;
            *reinterpret_cast<float4*>(out_sp + (size_t)(pbase + pl) * N_STEPS + s0 + so) = os;
        }
    }

    out_lq[pbase + l] = lsq;
}

extern "C" void kernel_launch(void* const* d_in, const int* in_sizes, int n_in,
                              void* d_out, int out_size)
{
    (void)in_sizes; (void)n_in; (void)out_size;
    // Phase 1: build lambda(lv, t) table — 512 steps x 512 grid points
    tab_kernel<<<(N_STEPS * HALF_NPTS) / TPB1, TPB1>>>(
        (const float*)d_in[2], (const float*)d_in[3],
        (const float*)d_in[4], (const float*)d_in[5],
        (const float*)d_in[6], (const float*)d_in[7]);
    // Phase 2: SDE sweep with smem-table-interpolated lambda
    sde_kernel<<<N_PATHS / TPB2, TPB2>>>(
        (const float*)d_in[0], (const float*)d_in[1],
        (const float*)d_in[8],
        (float*)d_out);
}

// round 9
// speedup vs baseline: 10.5618x; 1.0492x over previous
#include <cuda_runtime.h>

#define N_PATHS 65536
#define N_STEPS 512

// piecewise-cubic lambda table: 64 segments per step, 4 nodes per segment
#define NSEG    64
#define NNODES  256              // 4 * NSEG evaluations per step
#define HALF_NODES 128
#define TILE    8

#define TPB1    128
#define TPB2    128
#define WARPS2  (TPB2/32)

// ---- constants (match reference float32 semantics) ----
#define DT_F        (1.0f/252.0f)
#define SQRT_DT_F   0.06299407883487120f     // sqrt(1/252)
#define KAPPA_F     2.72f
#define THETA_F     (-3.5f)
#define SIGMA_P_F   0.85f
#define RHO_F       (-0.85f)
#define CS_F        (0.5267826876426369f * 0.06299407883487120f) // sqrt(1-rho^2)*sqrt_dt
#define R_F         0.0373f
#define LAMBDA_MAX_F 3.0f
#define LOG_V_MIN_F (-7.0f)
#define LOG_V_MAX_F 2.0f
#define INV_NSTEPS  (1.0f/512.0f)
#define SEG_H       ((LOG_V_MAX_F - LOG_V_MIN_F) / (float)NSEG)      // 9/64
#define SEG_SCALE   ((float)NSEG / (LOG_V_MAX_F - LOG_V_MIN_F))      // 64/9

// scratch (device globals = legal scratch)
__device__ float  g_node[N_STEPS * NNODES];       // lambda at segment nodes
__device__ float4 g_coef[N_STEPS * NSEG];         // monomial cubic coeffs per segment

typedef unsigned long long ull;

// ---- packed f32x2 helpers (Blackwell fma.rn.f32x2) ----
__device__ __forceinline__ ull pack2(float a, float b) {
    ull r; asm("mov.b64 %0, {%1, %2};" : "=l"(r) : "f"(a), "f"(b)); return r;
}
__device__ __forceinline__ void unpack2(ull v, float& a, float& b) {
    asm("mov.b64 {%0, %1}, %2;" : "=f"(a), "=f"(b) : "l"(v));
}
__device__ __forceinline__ ull fma2(ull a, ull b, ull c) {
    ull d; asm("fma.rn.f32x2 %0, %1, %2, %3;" : "=l"(d) : "l"(a), "l"(b), "l"(c)); return d;
}
__device__ __forceinline__ ull mul2(ull a, ull b) {
    ull d; asm("mul.rn.f32x2 %0, %1, %2;" : "=l"(d) : "l"(a), "l"(b)); return d;
}

__device__ __forceinline__ float fast_tanh(float x) {
    float y;
    asm("tanh.approx.f32 %0, %1;" : "=f"(y) : "f"(x));
    return y;
}

// 5-op gelu on a pair (validated): gelu(x)=fma(0.5x, tanh(u), 0.5x)
__device__ __forceinline__ ull gelu2(ull x, ull GA, ull GB, ull GH) {
    ull x2 = mul2(x, x);
    ull u  = mul2(x, fma2(GA, x2, GB));
    ull hx = mul2(GH, x);
    float ulo, uhi; unpack2(u, ulo, uhi);
    ull tp = pack2(fast_tanh(ulo), fast_tanh(uhi));
    return fma2(hx, tp, hx);
}

// ============================================================================
// Phase 1a: evaluate lambda at segment nodes. One thread = MLP at 2 nodes
// (f32x2 lanes) for one time step. Same pair-MLP code validated R4..R8.
// Node n (0..255): segment j = n>>2, local node k = n&3 at u = k/3.
// ============================================================================
__global__ __launch_bounds__(TPB1, 4)
void node_kernel(const float* __restrict__ W1,  const float* __restrict__ b1,
                 const float* __restrict__ W2,  const float* __restrict__ b2,
                 const float* __restrict__ W3,  const float* __restrict__ b3)
{
    __shared__ float sw1t[32], sb1[32];
    __shared__ ull   sw0d[32], sb2d[32], sw3d[32];
    __shared__ __align__(16) float sW2[1024];
    __shared__ float sb3s;

    const int tid = threadIdx.x;
    for (int i = tid; i < 1024; i += TPB1) sW2[i] = W2[i];
    if (tid < 32) {
        float w0 = W1[2 * tid];
        sw0d[tid] = pack2(w0, w0);
        sw1t[tid] = W1[2 * tid + 1];
        sb1[tid]  = b1[tid];
        float bb = b2[tid];
        sb2d[tid] = pack2(bb, bb);
        float w3 = W3[tid];
        sw3d[tid] = pack2(w3, w3);
    }
    if (tid == 0) sb3s = b3[0];
    __syncthreads();

    const float4* W2v = reinterpret_cast<const float4*>(sW2);
    const ull GA = pack2(0.0356774081363059f, 0.0356774081363059f);
    const ull GB = pack2(0.7978845608028654f, 0.7978845608028654f);
    const ull GH = pack2(0.5f, 0.5f);

    const int gid = blockIdx.x * TPB1 + tid;       // 0 .. N_STEPS*HALF_NODES-1
    const int s   = gid >> 7;                      // / HALF_NODES
    const int r   = gid & (HALF_NODES - 1);        // node index (lane A); lane B = r+128
    const float t = (float)s * INV_NSTEPS;

    const int jA = r >> 2, kA = r & 3;
    const float lvA = fmaf((float)jA + (float)kA * 0.3333333333f, SEG_H, LOG_V_MIN_F);
    const float lvB = lvA + 32.0f * SEG_H;         // node r+128 = segment jA+32, same k
    const ull lvp = pack2(lvA, lvB);

    // layer 1
    ull h1[32];
    #pragma unroll
    for (int k = 0; k < 32; k++) {
        float c1 = fmaf(sw1t[k], t, sb1[k]);
        ull arg = fma2(sw0d[k], lvp, pack2(c1, c1));
        h1[k] = gelu2(arg, GA, GB, GH);
    }

    // layer 2 + layer 3 reduction (validated structure)
    ull red0 = pack2(0.0f, 0.0f);
    ull red1 = pack2(0.0f, 0.0f);
    #pragma unroll 1
    for (int jg = 0; jg < 8; jg++) {
        const int j0 = jg * 4;
        ull a0 = sb2d[j0 + 0];
        ull a1 = sb2d[j0 + 1];
        ull a2 = sb2d[j0 + 2];
        ull a3 = sb2d[j0 + 3];
        #pragma unroll
        for (int k4 = 0; k4 < 8; k4++) {
            ull h0 = h1[4 * k4 + 0];
            ull hA = h1[4 * k4 + 1];
            ull hB = h1[4 * k4 + 2];
            ull hC = h1[4 * k4 + 3];
            float4 q0 = W2v[(j0 + 0) * 8 + k4];
            float4 q1 = W2v[(j0 + 1) * 8 + k4];
            float4 q2 = W2v[(j0 + 2) * 8 + k4];
            float4 q3 = W2v[(j0 + 3) * 8 + k4];
            a0 = fma2(pack2(q0.x, q0.x), h0, a0);
            a0 = fma2(pack2(q0.y, q0.y), hA, a0);
            a0 = fma2(pack2(q0.z, q0.z), hB, a0);
            a0 = fma2(pack2(q0.w, q0.w), hC, a0);
            a1 = fma2(pack2(q1.x, q1.x), h0, a1);
            a1 = fma2(pack2(q1.y, q1.y), hA, a1);
            a1 = fma2(pack2(q1.z, q1.z), hB, a1);
            a1 = fma2(pack2(q1.w, q1.w), hC, a1);
            a2 = fma2(pack2(q2.x, q2.x), h0, a2);
            a2 = fma2(pack2(q2.y, q2.y), hA, a2);
            a2 = fma2(pack2(q2.z, q2.z), hB, a2);
            a2 = fma2(pack2(q2.w, q2.w), hC, a2);
            a3 = fma2(pack2(q3.x, q3.x), h0, a3);
            a3 = fma2(pack2(q3.y, q3.y), hA, a3);
            a3 = fma2(pack2(q3.z, q3.z), hB, a3);
            a3 = fma2(pack2(q3.w, q3.w), hC, a3);
        }
        red0 = fma2(sw3d[j0 + 0], gelu2(a0, GA, GB, GH), red0);
        red1 = fma2(sw3d[j0 + 1], gelu2(a1, GA, GB, GH), red1);
        red0 = fma2(sw3d[j0 + 2], gelu2(a2, GA, GB, GH), red0);
        red1 = fma2(sw3d[j0 + 3], gelu2(a3, GA, GB, GH), red1);
    }
    float rA0, rB0, rA1, rB1;
    unpack2(red0, rA0, rB0);
    unpack2(red1, rA1, rB1);
    float rawA = (rA0 + rA1) + sb3s;
    float rawB = (rB0 + rB1) + sb3s;

    g_node[s * NNODES + r]              = LAMBDA_MAX_F * tanhf(rawA);
    g_node[s * NNODES + r + HALF_NODES] = LAMBDA_MAX_F * tanhf(rawB);
}

// ============================================================================
// Phase 1b: 4 node values per segment -> monomial cubic coefficients.
// Nodes at u = 0, 1/3, 2/3, 1:
//   c0 = f0
//   c1 = ( -11 f0 + 18 f1 -  9 f2 + 2 f3 ) / 2
//   c2 = (  18 f0 - 45 f1 + 36 f2 - 9 f3 ) / 2
//   c3 = (  -9 f0 + 27 f1 - 27 f2 + 9 f3 ) / 2
// ============================================================================
__global__ __launch_bounds__(TPB1, 4)
void coef_kernel()
{
    const int gid = blockIdx.x * TPB1 + threadIdx.x;   // 0 .. N_STEPS*NSEG-1
    const int s = gid >> 6;
    const int j = gid & (NSEG - 1);
    const float4 f = reinterpret_cast<const float4*>(g_node + s * NNODES)[j];
    float4 c;
    c.x = f.x;
    c.y = 0.5f * (-11.0f * f.x + 18.0f * f.y - 9.0f  * f.z + 2.0f * f.w);
    c.z = 0.5f * ( 18.0f * f.x - 45.0f * f.y + 36.0f * f.z - 9.0f * f.w);
    c.w = 0.5f * ( -9.0f * f.x + 27.0f * f.y - 27.0f * f.z + 9.0f * f.w);
    g_coef[s * NSEG + j] = c;
}

// ============================================================================
// Phase 2: SDE sweep. Lambda = cubic Horner on ONE LDS.128 gather per step
// from an 8-step x 64-segment coefficient tile (8 KB smem).
// ============================================================================
__global__ __launch_bounds__(TPB2, 4)
void sde_kernel(const float* __restrict__ z1, const float* __restrict__ z2,
                const float* __restrict__ init_log_v,
                float* __restrict__ out)
{
    __shared__ float sz1[WARPS2][32][TILE + 1];
    __shared__ float sz2[WARPS2][32][TILE + 1];
    __shared__ float sov[WARPS2][32][TILE + 1];
    __shared__ float sos[WARPS2][32][TILE + 1];
    __shared__ __align__(16) float4 scoef[TILE][NSEG];   // 8 KB coeff tile

    const int tid = threadIdx.x;
    const int w = tid >> 5;
    const int l = tid & 31;
    const int pbase = blockIdx.x * TPB2 + w * 32;

    const float* z1w = z1 + (size_t)pbase * N_STEPS;
    const float* z2w = z2 + (size_t)pbase * N_STEPS;
    float* out_lv = out;
    float* out_sp = out + (size_t)N_PATHS * N_STEPS;
    float* out_lq = out + 2 * (size_t)N_PATHS * N_STEPS;

    float lv  = init_log_v[0];
    float ls  = 0.0f;
    float lsq = 0.0f;

    const int pl_lo = (l >> 1);        // 0..15
    const int so    = (l & 1) * 4;     // 0 or 4

    #pragma unroll 1
    for (int s0 = 0; s0 < N_STEPS; s0 += TILE) {
        __syncthreads();   // previous tile's smem reads complete

        // ---- refill coeff tile: 8 steps x 64 float4 = 512 float4, coalesced ----
        {
            const float4* src = g_coef + (size_t)s0 * NSEG;
            float4* dst = &scoef[0][0];
            #pragma unroll
            for (int i = 0; i < (TILE * NSEG) / TPB2; i++)   // 4 iters
                dst[tid + i * TPB2] = src[tid + i * TPB2];
        }

        // ---- stage z (coalesced LDG.128 -> padded smem), 32 rows x 8 cols ----
        #pragma unroll
        for (int it = 0; it < 2; it++) {
            int pl = it * 16 + pl_lo;
            float4 v1 = *reinterpret_cast<const float4*>(z1w + (size_t)pl * N_STEPS + s0 + so);
            float4 v2 = *reinterpret_cast<const float4*>(z2w + (size_t)pl * N_STEPS + s0 + so);
            sz1[w][pl][so]     = v1.x; sz1[w][pl][so + 1] = v1.y;
            sz1[w][pl][so + 2] = v1.z; sz1[w][pl][so + 3] = v1.w;
            sz2[w][pl][so]     = v2.x; sz2[w][pl][so + 1] = v2.y;
            sz2[w][pl][so + 2] = v2.z; sz2[w][pl][so + 3] = v2.w;
        }
        __syncthreads();   // scoef + z tiles visible to all

        // ---- 8 sequential SDE steps ----
        #pragma unroll 1
        for (int si = 0; si < TILE; si++) {
            // lambda via per-segment cubic: lv in [-7,2] guaranteed by the clip
            float x  = (lv - LOG_V_MIN_F) * SEG_SCALE;     // [0, 64]
            float fj = fminf(floorf(x), (float)(NSEG - 1));
            float u  = x - fj;                             // [0, 1]
            int   j  = (int)fj;
            float4 c = scoef[si][j];
            float lam = fmaf(fmaf(fmaf(c.w, u, c.z), u, c.y), u, c.x);

            // SDE update (identical numerics to validated kernels)
            float z1s = sz1[w][l][si];
            float z2s = sz2[w][l][si];
            float dwv = SQRT_DT_F * z1s;
            float dws = fmaf(RHO_F, dwv, CS_F * z2s);

            float mu_p    = (KAPPA_F * (THETA_F - lv)) * DT_F;
            float drift_q = mu_p - (lam * SIGMA_P_F) * DT_F;
            float lv_next = lv + drift_q + SIGMA_P_F * dwv;
            lv_next = fminf(fmaxf(lv_next, LOG_V_MIN_F), LOG_V_MAX_F);

            float ev  = __expf(lv);
            float vol = sqrtf(fmaxf(ev, 1e-10f));
            float ls_next = ls + (R_F - 0.5f * ev) * DT_F + vol * dws;

            lsq = fmaf(lam * lam, DT_F, lsq);

            sov[w][l][si] = lv_next;
            sos[w][l][si] = __expf(ls_next);

            lv = lv_next;
            ls = ls_next;
        }
        __syncwarp();   // sov/sos per-warp writes visible before flush

        // ---- flush outputs (padded smem -> coalesced STG.128) ----
        #pragma unroll
        for (int it = 0; it < 2; it++) {
            int pl = it * 16 + pl_lo;
            float4 ov, os;
            ov.x = sov[w][pl][so];     ov.y = sov[w][pl][so + 1];
            ov.z = sov[w][pl][so + 2]; ov.w = sov[w][pl][so + 3];
            os.x = sos[w][pl][so];     os.y = sos[w][pl][so + 1];
            os.z = sos[w][pl][so + 2]; os.w = sos[w][pl][so + 3];
            *reinterpret_cast<float4*>(out_lv + (size_t)(pbase + pl) * N_STEPS + s0 + so) = ov;
            *reinterpret_cast<float4*>(out_sp + (size_t)(pbase + pl) * N_STEPS + s0 + so) = os;
        }
    }

    out_lq[pbase + l] = lsq;
}

extern "C" void kernel_launch(void* const* d_in, const int* in_sizes, int n_in,
                              void* d_out, int out_size)
{
    (void)in_sizes; (void)n_in; (void)out_size;
    // Phase 1a: lambda at 256 segment nodes per step
    node_kernel<<<(N_STEPS * HALF_NODES) / TPB1, TPB1>>>(
        (const float*)d_in[2], (const float*)d_in[3],
        (const float*)d_in[4], (const float*)d_in[5],
        (const float*)d_in[6], (const float*)d_in[7]);
    // Phase 1b: node values -> cubic coefficients
    coef_kernel<<<(N_STEPS * NSEG) / TPB1, TPB1>>>();
    // Phase 2: SDE sweep with piecewise-cubic lambda
    sde_kernel<<<N_PATHS / TPB2, TPB2>>>(
        (const float*)d_in[0], (const float*)d_in[1],
        (const float*)d_in[8],
        (float*)d_out);
}

// round 10
// speedup vs baseline: 18.4877x; 1.7504x over previous
#include <cuda_runtime.h>

#define N_PATHS 65536
#define N_STEPS 512

// piecewise-cubic lambda table: 64 segments per step, 4 nodes per segment
#define NSEG    64
#define NNODES  256
#define HALF_NODES 128
#define TILE    16

#define TPB1    128
#define TPB2    128
#define WARPS2  (TPB2/32)

// ---- constants (match reference float32 semantics) ----
#define DT_F        (1.0f/252.0f)
#define SQRT_DT_F   0.06299407883487120f     // sqrt(1/252)
#define KAPPA_F     2.72f
#define THETA_F     (-3.5f)
#define SIGMA_P_F   0.85f
#define RHO_F       (-0.85f)
#define CS_F        (0.5267826876426369f * 0.06299407883487120f) // sqrt(1-rho^2)*sqrt_dt
#define R_F         0.0373f
#define LAMBDA_MAX_F 3.0f
#define LOG_V_MIN_F (-7.0f)
#define LOG_V_MAX_F 2.0f
#define INV_NSTEPS  (1.0f/512.0f)
#define SEG_H       ((LOG_V_MAX_F - LOG_V_MIN_F) / (float)NSEG)      // 9/64
#define SEG_SCALE   ((float)NSEG / (LOG_V_MAX_F - LOG_V_MIN_F))      // 64/9
#define SEG_OFS     (-(LOG_V_MIN_F) * SEG_SCALE)

// scratch (device globals = legal scratch)
__device__ float  g_node[N_STEPS * NNODES];       // lambda at segment nodes
__device__ float4 g_coef[N_STEPS * NSEG];         // monomial cubic coeffs per segment

typedef unsigned long long ull;

// ---- packed f32x2 helpers (Blackwell fma.rn.f32x2) ----
__device__ __forceinline__ ull pack2(float a, float b) {
    ull r; asm("mov.b64 %0, {%1, %2};" : "=l"(r) : "f"(a), "f"(b)); return r;
}
__device__ __forceinline__ void unpack2(ull v, float& a, float& b) {
    asm("mov.b64 {%0, %1}, %2;" : "=f"(a), "=f"(b) : "l"(v));
}
__device__ __forceinline__ ull fma2(ull a, ull b, ull c) {
    ull d; asm("fma.rn.f32x2 %0, %1, %2, %3;" : "=l"(d) : "l"(a), "l"(b), "l"(c)); return d;
}
__device__ __forceinline__ ull mul2(ull a, ull b) {
    ull d; asm("mul.rn.f32x2 %0, %1, %2;" : "=l"(d) : "l"(a), "l"(b)); return d;
}

__device__ __forceinline__ float fast_tanh(float x) {
    float y;
    asm("tanh.approx.f32 %0, %1;" : "=f"(y) : "f"(x));
    return y;
}

// 5-op gelu on a pair (validated): gelu(x)=fma(0.5x, tanh(u), 0.5x)
__device__ __forceinline__ ull gelu2(ull x, ull GA, ull GB, ull GH) {
    ull x2 = mul2(x, x);
    ull u  = mul2(x, fma2(GA, x2, GB));
    ull hx = mul2(GH, x);
    float ulo, uhi; unpack2(u, ulo, uhi);
    ull tp = pack2(fast_tanh(ulo), fast_tanh(uhi));
    return fma2(hx, tp, hx);
}

// ============================================================================
// Phase 1a: evaluate lambda at segment nodes (validated R9).
// ============================================================================
__global__ __launch_bounds__(TPB1, 4)
void node_kernel(const float* __restrict__ W1,  const float* __restrict__ b1,
                 const float* __restrict__ W2,  const float* __restrict__ b2,
                 const float* __restrict__ W3,  const float* __restrict__ b3)
{
    __shared__ float sw1t[32], sb1[32];
    __shared__ ull   sw0d[32], sb2d[32], sw3d[32];
    __shared__ __align__(16) float sW2[1024];
    __shared__ float sb3s;

    const int tid = threadIdx.x;
    for (int i = tid; i < 1024; i += TPB1) sW2[i] = W2[i];
    if (tid < 32) {
        float w0 = W1[2 * tid];
        sw0d[tid] = pack2(w0, w0);
        sw1t[tid] = W1[2 * tid + 1];
        sb1[tid]  = b1[tid];
        float bb = b2[tid];
        sb2d[tid] = pack2(bb, bb);
        float w3 = W3[tid];
        sw3d[tid] = pack2(w3, w3);
    }
    if (tid == 0) sb3s = b3[0];
    __syncthreads();

    const float4* W2v = reinterpret_cast<const float4*>(sW2);
    const ull GA = pack2(0.0356774081363059f, 0.0356774081363059f);
    const ull GB = pack2(0.7978845608028654f, 0.7978845608028654f);
    const ull GH = pack2(0.5f, 0.5f);

    const int gid = blockIdx.x * TPB1 + tid;
    const int s   = gid >> 7;
    const int r   = gid & (HALF_NODES - 1);
    const float t = (float)s * INV_NSTEPS;

    const int jA = r >> 2, kA = r & 3;
    const float lvA = fmaf((float)jA + (float)kA * 0.3333333333f, SEG_H, LOG_V_MIN_F);
    const float lvB = lvA + 32.0f * SEG_H;
    const ull lvp = pack2(lvA, lvB);

    ull h1[32];
    #pragma unroll
    for (int k = 0; k < 32; k++) {
        float c1 = fmaf(sw1t[k], t, sb1[k]);
        ull arg = fma2(sw0d[k], lvp, pack2(c1, c1));
        h1[k] = gelu2(arg, GA, GB, GH);
    }

    ull red0 = pack2(0.0f, 0.0f);
    ull red1 = pack2(0.0f, 0.0f);
    #pragma unroll 1
    for (int jg = 0; jg < 8; jg++) {
        const int j0 = jg * 4;
        ull a0 = sb2d[j0 + 0];
        ull a1 = sb2d[j0 + 1];
        ull a2 = sb2d[j0 + 2];
        ull a3 = sb2d[j0 + 3];
        #pragma unroll
        for (int k4 = 0; k4 < 8; k4++) {
            ull h0 = h1[4 * k4 + 0];
            ull hA = h1[4 * k4 + 1];
            ull hB = h1[4 * k4 + 2];
            ull hC = h1[4 * k4 + 3];
            float4 q0 = W2v[(j0 + 0) * 8 + k4];
            float4 q1 = W2v[(j0 + 1) * 8 + k4];
            float4 q2 = W2v[(j0 + 2) * 8 + k4];
            float4 q3 = W2v[(j0 + 3) * 8 + k4];
            a0 = fma2(pack2(q0.x, q0.x), h0, a0);
            a0 = fma2(pack2(q0.y, q0.y), hA, a0);
            a0 = fma2(pack2(q0.z, q0.z), hB, a0);
            a0 = fma2(pack2(q0.w, q0.w), hC, a0);
            a1 = fma2(pack2(q1.x, q1.x), h0, a1);
            a1 = fma2(pack2(q1.y, q1.y), hA, a1);
            a1 = fma2(pack2(q1.z, q1.z), hB, a1);
            a1 = fma2(pack2(q1.w, q1.w), hC, a1);
            a2 = fma2(pack2(q2.x, q2.x), h0, a2);
            a2 = fma2(pack2(q2.y, q2.y), hA, a2);
            a2 = fma2(pack2(q2.z, q2.z), hB, a2);
            a2 = fma2(pack2(q2.w, q2.w), hC, a2);
            a3 = fma2(pack2(q3.x, q3.x), h0, a3);
            a3 = fma2(pack2(q3.y, q3.y), hA, a3);
            a3 = fma2(pack2(q3.z, q3.z), hB, a3);
            a3 = fma2(pack2(q3.w, q3.w), hC, a3);
        }
        red0 = fma2(sw3d[j0 + 0], gelu2(a0, GA, GB, GH), red0);
        red1 = fma2(sw3d[j0 + 1], gelu2(a1, GA, GB, GH), red1);
        red0 = fma2(sw3d[j0 + 2], gelu2(a2, GA, GB, GH), red0);
        red1 = fma2(sw3d[j0 + 3], gelu2(a3, GA, GB, GH), red1);
    }
    float rA0, rB0, rA1, rB1;
    unpack2(red0, rA0, rB0);
    unpack2(red1, rA1, rB1);
    float rawA = (rA0 + rA1) + sb3s;
    float rawB = (rB0 + rB1) + sb3s;

    g_node[s * NNODES + r]              = LAMBDA_MAX_F * tanhf(rawA);
    g_node[s * NNODES + r + HALF_NODES] = LAMBDA_MAX_F * tanhf(rawB);
}

// ============================================================================
// Phase 1b: 4 node values (u = 0,1/3,2/3,1) -> monomial cubic coefficients.
// ============================================================================
__global__ __launch_bounds__(TPB1, 4)
void coef_kernel()
{
    const int gid = blockIdx.x * TPB1 + threadIdx.x;
    const int s = gid >> 6;
    const int j = gid & (NSEG - 1);
    const float4 f = reinterpret_cast<const float4*>(g_node + s * NNODES)[j];
    float4 c;
    c.x = f.x;
    c.y = 0.5f * (-11.0f * f.x + 18.0f * f.y - 9.0f  * f.z + 2.0f * f.w);
    c.z = 0.5f * ( 18.0f * f.x - 45.0f * f.y + 36.0f * f.z - 9.0f * f.w);
    c.w = 0.5f * ( -9.0f * f.x + 27.0f * f.y - 27.0f * f.z + 9.0f * f.w);
    g_coef[s * NSEG + j] = c;
}

// ============================================================================
// Phase 2: SDE sweep. TILE=16, z staged through smem with REGISTER
// double-buffering (next tile's z prefetched into regs during the step loop,
// hiding DRAM latency), outputs reuse the z buffers in place. Cubic Horner
// lambda from a 16-step x 64-segment smem coeff tile.
// ============================================================================
__global__ __launch_bounds__(TPB2, 4)
void sde_kernel(const float* __restrict__ z1, const float* __restrict__ z2,
                const float* __restrict__ init_log_v,
                float* __restrict__ out)
{
    __shared__ float sza[WARPS2][32][TILE + 1];   // z1 in -> log_v out
    __shared__ float szb[WARPS2][32][TILE + 1];   // z2 in -> spot  out
    __shared__ __align__(16) float4 scoef[TILE][NSEG];   // 16 KB coeff tile

    const int tid = threadIdx.x;
    const int w = tid >> 5;
    const int l = tid & 31;
    const int pbase = blockIdx.x * TPB2 + w * 32;

    const float* z1w = z1 + (size_t)pbase * N_STEPS;
    const float* z2w = z2 + (size_t)pbase * N_STEPS;
    float* out_lv = out;
    float* out_sp = out + (size_t)N_PATHS * N_STEPS;
    float* out_lq = out + 2 * (size_t)N_PATHS * N_STEPS;

    float lv  = init_log_v[0];
    float ls  = 0.0f;
    float lsq = 0.0f;

    const int pl_lo = (l >> 2);        // 0..7
    const int so    = (l & 3) * 4;     // 0,4,8,12

    // ---- initial z prefetch (tile 0) into registers ----
    float4 r1[4], r2[4];
    #pragma unroll
    for (int it = 0; it < 4; it++) {
        int pl = it * 8 + pl_lo;
        r1[it] = *reinterpret_cast<const float4*>(z1w + (size_t)pl * N_STEPS + so);
        r2[it] = *reinterpret_cast<const float4*>(z2w + (size_t)pl * N_STEPS + so);
    }

    #pragma unroll 1
    for (int s0 = 0; s0 < N_STEPS; s0 += TILE) {
        __syncthreads();   // previous tile's flush reads + coef reads complete

        // ---- deposit prefetched z into padded smem ----
        #pragma unroll
        for (int it = 0; it < 4; it++) {
            int pl = it * 8 + pl_lo;
            sza[w][pl][so]     = r1[it].x; sza[w][pl][so + 1] = r1[it].y;
            sza[w][pl][so + 2] = r1[it].z; sza[w][pl][so + 3] = r1[it].w;
            szb[w][pl][so]     = r2[it].x; szb[w][pl][so + 1] = r2[it].y;
            szb[w][pl][so + 2] = r2[it].z; szb[w][pl][so + 3] = r2[it].w;
        }

        // ---- refill coeff tile: 16 steps x 64 float4 = 1024 float4 ----
        {
            const float4* src = g_coef + (size_t)s0 * NSEG;
            float4* dst = &scoef[0][0];
            #pragma unroll
            for (int i = 0; i < (TILE * NSEG) / TPB2; i++)   // 8 iters
                dst[tid + i * TPB2] = src[tid + i * TPB2];
        }

        // ---- issue NEXT tile's z loads (latency hidden under step loop) ----
        if (s0 + TILE < N_STEPS) {
            #pragma unroll
            for (int it = 0; it < 4; it++) {
                int pl = it * 8 + pl_lo;
                r1[it] = *reinterpret_cast<const float4*>(z1w + (size_t)pl * N_STEPS + s0 + TILE + so);
                r2[it] = *reinterpret_cast<const float4*>(z2w + (size_t)pl * N_STEPS + s0 + TILE + so);
            }
        }
        __syncthreads();   // z + coef tiles visible to all

        // ---- 16 sequential SDE steps (fully unrolled for cross-step overlap) ----
        #pragma unroll
        for (int si = 0; si < TILE; si++) {
            // lambda via per-segment cubic: lv in [-7,2] guaranteed by the clip
            float x  = fmaf(lv, SEG_SCALE, SEG_OFS);       // [0, 64]
            float fj = fminf(fmaxf(floorf(x), 0.0f), 63.0f);
            float u  = x - fj;
            int   j  = (int)fj;
            float4 c = scoef[si][j];
            float lam = fmaf(fmaf(fmaf(c.w, u, c.z), u, c.y), u, c.x);

            float z1s = sza[w][l][si];
            float z2s = szb[w][l][si];
            float dwv = SQRT_DT_F * z1s;
            float dws = fmaf(RHO_F, dwv, CS_F * z2s);

            float mu_p    = (KAPPA_F * (THETA_F - lv)) * DT_F;
            float drift_q = mu_p - (lam * SIGMA_P_F) * DT_F;
            float lv_next = lv + drift_q + SIGMA_P_F * dwv;
            lv_next = fminf(fmaxf(lv_next, LOG_V_MIN_F), LOG_V_MAX_F);

            // lv >= -7  =>  exp(lv) >= 9e-4 >> 1e-10: vol = exp(lv/2), ev = vol^2
            float vol = __expf(0.5f * lv);
            float ev  = vol * vol;
            float ls_next = ls + (R_F - 0.5f * ev) * DT_F + vol * dws;

            lsq = fmaf(lam * lam, DT_F, lsq);

            sza[w][l][si] = lv_next;
            szb[w][l][si] = __expf(ls_next);

            lv = lv_next;
            ls = ls_next;
        }
        __syncwarp();   // own-warp sza/szb writes visible before flush

        // ---- flush outputs (padded smem -> coalesced STG.128) ----
        #pragma unroll
        for (int it = 0; it < 4; it++) {
            int pl = it * 8 + pl_lo;
            float4 ov, os;
            ov.x = sza[w][pl][so];     ov.y = sza[w][pl][so + 1];
            ov.z = sza[w][pl][so + 2]; ov.w = sza[w][pl][so + 3];
            os.x = szb[w][pl][so];     os.y = szb[w][pl][so + 1];
            os.z = szb[w][pl][so + 2]; os.w = szb[w][pl][so + 3];
            *reinterpret_cast<float4*>(out_lv + (size_t)(pbase + pl) * N_STEPS + s0 + so) = ov;
            *reinterpret_cast<float4*>(out_sp + (size_t)(pbase + pl) * N_STEPS + s0 + so) = os;
        }
    }

    out_lq[pbase + l] = lsq;
}

extern "C" void kernel_launch(void* const* d_in, const int* in_sizes, int n_in,
                              void* d_out, int out_size)
{
    (void)in_sizes; (void)n_in; (void)out_size;
    // Phase 1a: lambda at 256 segment nodes per step
    node_kernel<<<(N_STEPS * HALF_NODES) / TPB1, TPB1>>>(
        (const float*)d_in[2], (const float*)d_in[3],
        (const float*)d_in[4], (const float*)d_in[5],
        (const float*)d_in[6], (const float*)d_in[7]);
    // Phase 1b: node values -> cubic coefficients
    coef_kernel<<<(N_STEPS * NSEG) / TPB1, TPB1>>>();
    // Phase 2: SDE sweep with piecewise-cubic lambda
    sde_kernel<<<N_PATHS / TPB2, TPB2>>>(
        (const float*)d_in[0], (const float*)d_in[1],
        (const float*)d_in[8],
        (float*)d_out);
}

// round 11
// speedup vs baseline: 21.6511x; 1.1711x over previous
#include <cuda_runtime.h>

#define N_PATHS 65536
#define N_STEPS 512

// piecewise-cubic lambda table: 32 segments per step, 4 nodes per segment
#define NSEG    32
#define NNODES  128
#define HALF_NODES 64
#define TILE    16

#define TPB1    128
#define TPB2    64
#define WARPS2  (TPB2/32)

// ---- constants (match reference float32 semantics) ----
#define DT_F        (1.0f/252.0f)
#define SQRT_DT_F   0.06299407883487120f     // sqrt(1/252)
#define KAPPA_F     2.72f
#define THETA_F     (-3.5f)
#define SIGMA_P_F   0.85f
#define RHO_F       (-0.85f)
#define CS_F        (0.5267826876426369f * 0.06299407883487120f) // sqrt(1-rho^2)*sqrt_dt
#define R_F         0.0373f
#define LAMBDA_MAX_F 3.0f
#define LOG_V_MIN_F (-7.0f)
#define LOG_V_MAX_F 2.0f
#define INV_NSTEPS  (1.0f/512.0f)
#define SEG_H       ((LOG_V_MAX_F - LOG_V_MIN_F) / (float)NSEG)      // 9/32
#define SEG_SCALE   ((float)NSEG / (LOG_V_MAX_F - LOG_V_MIN_F))      // 32/9
#define SEG_OFS     (-(LOG_V_MIN_F) * SEG_SCALE)
// drift restructure: lv + kappa*(theta-lv)*dt = A*lv + B
#define DRIFT_A     (1.0f - KAPPA_F * DT_F)
#define DRIFT_B     (KAPPA_F * THETA_F * DT_F)
#define NEG_SGDT    (-(SIGMA_P_F * DT_F))

// scratch (device globals = legal scratch)
__device__ float  g_node[N_STEPS * NNODES];       // lambda at segment nodes
__device__ float4 g_coef[N_STEPS * NSEG];         // monomial cubic coeffs per segment

typedef unsigned long long ull;

// ---- packed f32x2 helpers (Blackwell fma.rn.f32x2) ----
__device__ __forceinline__ ull pack2(float a, float b) {
    ull r; asm("mov.b64 %0, {%1, %2};" : "=l"(r) : "f"(a), "f"(b)); return r;
}
__device__ __forceinline__ void unpack2(ull v, float& a, float& b) {
    asm("mov.b64 {%0, %1}, %2;" : "=f"(a), "=f"(b) : "l"(v));
}
__device__ __forceinline__ ull fma2(ull a, ull b, ull c) {
    ull d; asm("fma.rn.f32x2 %0, %1, %2, %3;" : "=l"(d) : "l"(a), "l"(b), "l"(c)); return d;
}
__device__ __forceinline__ ull mul2(ull a, ull b) {
    ull d; asm("mul.rn.f32x2 %0, %1, %2;" : "=l"(d) : "l"(a), "l"(b)); return d;
}

__device__ __forceinline__ float fast_tanh(float x) {
    float y;
    asm("tanh.approx.f32 %0, %1;" : "=f"(y) : "f"(x));
    return y;
}

// 5-op gelu on a pair (validated): gelu(x)=fma(0.5x, tanh(u), 0.5x)
__device__ __forceinline__ ull gelu2(ull x, ull GA, ull GB, ull GH) {
    ull x2 = mul2(x, x);
    ull u  = mul2(x, fma2(GA, x2, GB));
    ull hx = mul2(GH, x);
    float ulo, uhi; unpack2(u, ulo, uhi);
    ull tp = pack2(fast_tanh(ulo), fast_tanh(uhi));
    return fma2(hx, tp, hx);
}

// ============================================================================
// Phase 1a: evaluate lambda at segment nodes (validated pair-MLP, R4..R10).
// Node n (0..127): segment j = n>>2, local node k = n&3 at u = k/3.
// Lane A = node r, lane B = node r+64 (segment j+16, same k).
// ============================================================================
__global__ __launch_bounds__(TPB1, 4)
void node_kernel(const float* __restrict__ W1,  const float* __restrict__ b1,
                 const float* __restrict__ W2,  const float* __restrict__ b2,
                 const float* __restrict__ W3,  const float* __restrict__ b3)
{
    __shared__ float sw1t[32], sb1[32];
    __shared__ ull   sw0d[32], sb2d[32], sw3d[32];
    __shared__ __align__(16) float sW2[1024];
    __shared__ float sb3s;

    const int tid = threadIdx.x;
    for (int i = tid; i < 1024; i += TPB1) sW2[i] = W2[i];
    if (tid < 32) {
        float w0 = W1[2 * tid];
        sw0d[tid] = pack2(w0, w0);
        sw1t[tid] = W1[2 * tid + 1];
        sb1[tid]  = b1[tid];
        float bb = b2[tid];
        sb2d[tid] = pack2(bb, bb);
        float w3 = W3[tid];
        sw3d[tid] = pack2(w3, w3);
    }
    if (tid == 0) sb3s = b3[0];
    __syncthreads();

    const float4* W2v = reinterpret_cast<const float4*>(sW2);
    const ull GA = pack2(0.0356774081363059f, 0.0356774081363059f);
    const ull GB = pack2(0.7978845608028654f, 0.7978845608028654f);
    const ull GH = pack2(0.5f, 0.5f);

    const int gid = blockIdx.x * TPB1 + tid;       // 0 .. N_STEPS*HALF_NODES-1
    const int s   = gid >> 6;                      // / HALF_NODES (64)
    const int r   = gid & (HALF_NODES - 1);
    const float t = (float)s * INV_NSTEPS;

    const int jA = r >> 2, kA = r & 3;
    const float lvA = fmaf((float)jA + (float)kA * 0.3333333333f, SEG_H, LOG_V_MIN_F);
    const float lvB = lvA + 16.0f * SEG_H;
    const ull lvp = pack2(lvA, lvB);

    ull h1[32];
    #pragma unroll
    for (int k = 0; k < 32; k++) {
        float c1 = fmaf(sw1t[k], t, sb1[k]);
        ull arg = fma2(sw0d[k], lvp, pack2(c1, c1));
        h1[k] = gelu2(arg, GA, GB, GH);
    }

    ull red0 = pack2(0.0f, 0.0f);
    ull red1 = pack2(0.0f, 0.0f);
    #pragma unroll 1
    for (int jg = 0; jg < 8; jg++) {
        const int j0 = jg * 4;
        ull a0 = sb2d[j0 + 0];
        ull a1 = sb2d[j0 + 1];
        ull a2 = sb2d[j0 + 2];
        ull a3 = sb2d[j0 + 3];
        #pragma unroll
        for (int k4 = 0; k4 < 8; k4++) {
            ull h0 = h1[4 * k4 + 0];
            ull hA = h1[4 * k4 + 1];
            ull hB = h1[4 * k4 + 2];
            ull hC = h1[4 * k4 + 3];
            float4 q0 = W2v[(j0 + 0) * 8 + k4];
            float4 q1 = W2v[(j0 + 1) * 8 + k4];
            float4 q2 = W2v[(j0 + 2) * 8 + k4];
            float4 q3 = W2v[(j0 + 3) * 8 + k4];
            a0 = fma2(pack2(q0.x, q0.x), h0, a0);
            a0 = fma2(pack2(q0.y, q0.y), hA, a0);
            a0 = fma2(pack2(q0.z, q0.z), hB, a0);
            a0 = fma2(pack2(q0.w, q0.w), hC, a0);
            a1 = fma2(pack2(q1.x, q1.x), h0, a1);
            a1 = fma2(pack2(q1.y, q1.y), hA, a1);
            a1 = fma2(pack2(q1.z, q1.z), hB, a1);
            a1 = fma2(pack2(q1.w, q1.w), hC, a1);
            a2 = fma2(pack2(q2.x, q2.x), h0, a2);
            a2 = fma2(pack2(q2.y, q2.y), hA, a2);
            a2 = fma2(pack2(q2.z, q2.z), hB, a2);
            a2 = fma2(pack2(q2.w, q2.w), hC, a2);
            a3 = fma2(pack2(q3.x, q3.x), h0, a3);
            a3 = fma2(pack2(q3.y, q3.y), hA, a3);
            a3 = fma2(pack2(q3.z, q3.z), hB, a3);
            a3 = fma2(pack2(q3.w, q3.w), hC, a3);
        }
        red0 = fma2(sw3d[j0 + 0], gelu2(a0, GA, GB, GH), red0);
        red1 = fma2(sw3d[j0 + 1], gelu2(a1, GA, GB, GH), red1);
        red0 = fma2(sw3d[j0 + 2], gelu2(a2, GA, GB, GH), red0);
        red1 = fma2(sw3d[j0 + 3], gelu2(a3, GA, GB, GH), red1);
    }
    float rA0, rB0, rA1, rB1;
    unpack2(red0, rA0, rB0);
    unpack2(red1, rA1, rB1);
    float rawA = (rA0 + rA1) + sb3s;
    float rawB = (rB0 + rB1) + sb3s;

    g_node[s * NNODES + r]              = LAMBDA_MAX_F * tanhf(rawA);
    g_node[s * NNODES + r + HALF_NODES] = LAMBDA_MAX_F * tanhf(rawB);
}

// ============================================================================
// Phase 1b: 4 node values (u = 0,1/3,2/3,1) -> monomial cubic coefficients.
// ============================================================================
__global__ __launch_bounds__(TPB1, 4)
void coef_kernel()
{
    const int gid = blockIdx.x * TPB1 + threadIdx.x;   // 0 .. N_STEPS*NSEG-1
    const int s = gid >> 5;
    const int j = gid & (NSEG - 1);
    const float4 f = reinterpret_cast<const float4*>(g_node + s * NNODES)[j];
    float4 c;
    c.x = f.x;
    c.y = 0.5f * (-11.0f * f.x + 18.0f * f.y - 9.0f  * f.z + 2.0f * f.w);
    c.z = 0.5f * ( 18.0f * f.x - 45.0f * f.y + 36.0f * f.z - 9.0f * f.w);
    c.w = 0.5f * ( -9.0f * f.x + 27.0f * f.y - 27.0f * f.z + 9.0f * f.w);
    g_coef[s * NSEG + j] = c;
}

// ============================================================================
// Phase 2: SDE sweep. TPB=64 / grid=1024 for fine wave balance (6-7 CTAs/SM
// instead of 3-4). Register double-buffered z staging, in-place output reuse,
// shortened per-step chain:
//   x=fma -> F2I.RD -> clamp -> LDS.128 -> Horner(3 fma) -> 1 fma -> clip
// with the drift base fmaf(A, lv, e) computed OFF the lambda chain.
// ============================================================================
__global__ __launch_bounds__(TPB2, 8)
void sde_kernel(const float* __restrict__ z1, const float* __restrict__ z2,
                const float* __restrict__ init_log_v,
                float* __restrict__ out)
{
    __shared__ float sza[WARPS2][32][TILE + 1];   // z1 in -> log_v out
    __shared__ float szb[WARPS2][32][TILE + 1];   // z2 in -> spot  out
    __shared__ __align__(16) float4 scoef[TILE][NSEG];   // 8 KB coeff tile

    const int tid = threadIdx.x;
    const int w = tid >> 5;
    const int l = tid & 31;
    const int pbase = blockIdx.x * TPB2 + w * 32;

    const float* z1w = z1 + (size_t)pbase * N_STEPS;
    const float* z2w = z2 + (size_t)pbase * N_STEPS;
    float* out_lv = out;
    float* out_sp = out + (size_t)N_PATHS * N_STEPS;
    float* out_lq = out + 2 * (size_t)N_PATHS * N_STEPS;

    float lv  = init_log_v[0];
    float ls  = 0.0f;
    float lsq = 0.0f;

    const int pl_lo = (l >> 2);        // 0..7
    const int so    = (l & 3) * 4;     // 0,4,8,12

    // ---- initial z prefetch (tile 0) into registers ----
    float4 r1[4], r2[4];
    #pragma unroll
    for (int it = 0; it < 4; it++) {
        int pl = it * 8 + pl_lo;
        r1[it] = *reinterpret_cast<const float4*>(z1w + (size_t)pl * N_STEPS + so);
        r2[it] = *reinterpret_cast<const float4*>(z2w + (size_t)pl * N_STEPS + so);
    }

    #pragma unroll 1
    for (int s0 = 0; s0 < N_STEPS; s0 += TILE) {
        __syncthreads();   // previous tile's flush reads + coef reads complete

        // ---- deposit prefetched z into padded smem ----
        #pragma unroll
        for (int it = 0; it < 4; it++) {
            int pl = it * 8 + pl_lo;
            sza[w][pl][so]     = r1[it].x; sza[w][pl][so + 1] = r1[it].y;
            sza[w][pl][so + 2] = r1[it].z; sza[w][pl][so + 3] = r1[it].w;
            szb[w][pl][so]     = r2[it].x; szb[w][pl][so + 1] = r2[it].y;
            szb[w][pl][so + 2] = r2[it].z; szb[w][pl][so + 3] = r2[it].w;
        }

        // ---- refill coeff tile: 16 steps x 32 float4 = 512 float4 ----
        {
            const float4* src = g_coef + (size_t)s0 * NSEG;
            float4* dst = &scoef[0][0];
            #pragma unroll
            for (int i = 0; i < (TILE * NSEG) / TPB2; i++)   // 8 iters
                dst[tid + i * TPB2] = src[tid + i * TPB2];
        }

        // ---- issue NEXT tile's z loads (latency hidden under step loop) ----
        if (s0 + TILE < N_STEPS) {
            #pragma unroll
            for (int it = 0; it < 4; it++) {
                int pl = it * 8 + pl_lo;
                r1[it] = *reinterpret_cast<const float4*>(z1w + (size_t)pl * N_STEPS + s0 + TILE + so);
                r2[it] = *reinterpret_cast<const float4*>(z2w + (size_t)pl * N_STEPS + s0 + TILE + so);
            }
        }
        __syncthreads();   // z + coef tiles visible to all

        // ---- 16 sequential SDE steps (fully unrolled) ----
        #pragma unroll
        for (int si = 0; si < TILE; si++) {
            // off-chain pieces (z known at tile start)
            float z1s = sza[w][l][si];
            float z2s = szb[w][l][si];
            float dwv = SQRT_DT_F * z1s;
            float dws = fmaf(RHO_F, dwv, CS_F * z2s);
            float e    = fmaf(SIGMA_P_F, dwv, DRIFT_B);   // sigma*dwv + kappa*theta*dt
            float base = fmaf(DRIFT_A, lv, e);            // (1-kappa dt)*lv + e

            // lambda chain: fma -> F2I.RD -> clamp -> LDS -> Horner
            float x  = fmaf(lv, SEG_SCALE, SEG_OFS);      // [0, 32]
            int   j  = __float2int_rd(x);
            j = max(min(j, NSEG - 1), 0);
            float u  = x - (float)j;
            float4 c = scoef[si][j];
            float lam = fmaf(fmaf(fmaf(c.w, u, c.z), u, c.y), u, c.x);

            float lv_next = fmaf(lam, NEG_SGDT, base);
            lv_next = fminf(fmaxf(lv_next, LOG_V_MIN_F), LOG_V_MAX_F);

            // lv >= -7 => exp(lv) >= 9e-4 >> 1e-10: vol = exp(lv/2), ev = vol^2
            float vol = __expf(0.5f * lv);
            float ev  = vol * vol;
            float ls_next = fmaf(vol, dws, fmaf(ev, -0.5f * DT_F, ls + R_F * DT_F));

            lsq = fmaf(lam * lam, DT_F, lsq);

            sza[w][l][si] = lv_next;
            szb[w][l][si] = __expf(ls_next);

            lv = lv_next;
            ls = ls_next;
        }
        __syncwarp();   // own-warp sza/szb writes visible before flush

        // ---- flush outputs (padded smem -> coalesced STG.128) ----
        #pragma unroll
        for (int it = 0; it < 4; it++) {
            int pl = it * 8 + pl_lo;
            float4 ov, os;
            ov.x = sza[w][pl][so];     ov.y = sza[w][pl][so + 1];
            ov.z = sza[w][pl][so + 2]; ov.w = sza[w][pl][so + 3];
            os.x = szb[w][pl][so];     os.y = szb[w][pl][so + 1];
            os.z = szb[w][pl][so + 2]; os.w = szb[w][pl][so + 3];
            *reinterpret_cast<float4*>(out_lv + (size_t)(pbase + pl) * N_STEPS + s0 + so) = ov;
            *reinterpret_cast<float4*>(out_sp + (size_t)(pbase + pl) * N_STEPS + s0 + so) = os;
        }
    }

    out_lq[pbase + l] = lsq;
}

extern "C" void kernel_launch(void* const* d_in, const int* in_sizes, int n_in,
                              void* d_out, int out_size)
{
    (void)in_sizes; (void)n_in; (void)out_size;
    // Phase 1a: lambda at 128 segment nodes per step
    node_kernel<<<(N_STEPS * HALF_NODES) / TPB1, TPB1>>>(
        (const float*)d_in[2], (const float*)d_in[3],
        (const float*)d_in[4], (const float*)d_in[5],
        (const float*)d_in[6], (const float*)d_in[7]);
    // Phase 1b: node values -> cubic coefficients
    coef_kernel<<<(N_STEPS * NSEG) / TPB1, TPB1>>>();
    // Phase 2: SDE sweep with piecewise-cubic lambda
    sde_kernel<<<N_PATHS / TPB2, TPB2>>>(
        (const float*)d_in[0], (const float*)d_in[1],
        (const float*)d_in[8],
        (float*)d_out);
}